// round 1
// baseline (speedup 1.0000x reference)
#include <cuda_runtime.h>
#include <math.h>
#include <stdint.h>

#define Bb 8
#define Nn 128
#define Tt 64
#define Dd 512
#define Hh 8
#define HD 64
#define TOPK 16
#define SCALE 0.125f   // 1/sqrt(64)

#define OUT0_ELEMS (Bb*Nn*Tt*Dd)        // 33554432
#define MEAN_ELEMS (Bb*Nn*Nn)           // 131072

// ---------------- scratch (static device allocation; no cudaMalloc) ----------------
__device__ float g_z[Bb*Nn*Dd];          // 2 MB
__device__ float g_q[Bb*Nn*Dd];          // 2 MB
__device__ float g_k[Bb*Nn*Dd];          // 2 MB
__device__ float g_wtq[Dd*Dd];
__device__ float g_wtk[Dd*Dd];
__device__ float g_wtv[Dd*Dd];
__device__ float g_wto[Dd*Dd];
__device__ float g_attn[Bb*Hh*Nn*Nn];    // 4 MB (dense, zeros outside topk)
__device__ float g_raw[Bb*Hh*Nn*Nn];     // 4 MB
__device__ int   g_idx[Bb*Hh*Nn*TOPK];
__device__ float g_w[Bb*Hh*Nn*TOPK];
__device__ float g_v[Bb*Nn*Tt*Dd];       // 128 MB
__device__ float g_mixed[Bb*Nn*Tt*Dd];   // 128 MB

// ---------------- weight transpose: wt[k][n] = w[n][k] ----------------
__global__ void transpose512(const float* __restrict__ w, float* __restrict__ wt) {
    __shared__ float tile[32][33];
    int bx = blockIdx.x * 32, by = blockIdx.y * 32;
    int tx = threadIdx.x, ty = threadIdx.y;
    #pragma unroll
    for (int i = 0; i < 32; i += 8)
        tile[ty + i][tx] = w[(by + ty + i) * Dd + bx + tx];
    __syncthreads();
    #pragma unroll
    for (int i = 0; i < 32; i += 8)
        wt[(bx + ty + i) * Dd + by + tx] = tile[tx][ty + i];
}

// ---------------- z_map = mean over T of h_map ----------------
__global__ void zmap_kernel(const float* __restrict__ hmap, float* __restrict__ z) {
    int bn = blockIdx.x;         // 0..B*N-1
    int d  = threadIdx.x;        // 0..511
    const float* p = hmap + (size_t)bn * Tt * Dd + d;
    float s = 0.f;
    #pragma unroll 8
    for (int t = 0; t < Tt; t++) s += p[t * Dd];
    z[bn * Dd + d] = s * (1.0f / Tt);
}

// ---------------- SGEMM: C[M,NC] = A[M,K] * Bm[K,NC]  (128x128x8 tiles, 8x8 micro) ----
// MODE 0: C = acc
// MODE 1: C = hval + acc * clamp(rs[(row/T)%N], 0, 1)
template <int MODE>
__global__ void __launch_bounds__(256)
sgemm128(const float* __restrict__ A, const float* __restrict__ Bm,
         float* __restrict__ C, int M, int NC, int K,
         const float* __restrict__ hval, const float* __restrict__ rs) {
    __shared__ float As[8][128];
    __shared__ float Bs[8][128];
    int tid  = threadIdx.x;
    int brow = blockIdx.y * 128, bcol = blockIdx.x * 128;
    int tr = (tid / 16) * 8, tc = (tid % 16) * 8;

    int aRow  = tid >> 1;            // 0..127
    int aCol4 = (tid & 1) * 4;       // 0 or 4
    int bRow  = tid >> 5;            // 0..7
    int bCol4 = (tid & 31) * 4;      // 0..124

    float acc[8][8];
    #pragma unroll
    for (int i = 0; i < 8; i++)
        #pragma unroll
        for (int j = 0; j < 8; j++) acc[i][j] = 0.f;

    for (int k0 = 0; k0 < K; k0 += 8) {
        float4 av = *(const float4*)(A + (size_t)(brow + aRow) * K + k0 + aCol4);
        As[aCol4 + 0][aRow] = av.x;
        As[aCol4 + 1][aRow] = av.y;
        As[aCol4 + 2][aRow] = av.z;
        As[aCol4 + 3][aRow] = av.w;
        *(float4*)&Bs[bRow][bCol4] =
            *(const float4*)(Bm + (size_t)(k0 + bRow) * NC + bcol + bCol4);
        __syncthreads();
        #pragma unroll
        for (int kk = 0; kk < 8; kk++) {
            float ar[8], br[8];
            *(float4*)&ar[0] = *(float4*)&As[kk][tr];
            *(float4*)&ar[4] = *(float4*)&As[kk][tr + 4];
            *(float4*)&br[0] = *(float4*)&Bs[kk][tc];
            *(float4*)&br[4] = *(float4*)&Bs[kk][tc + 4];
            #pragma unroll
            for (int i = 0; i < 8; i++)
                #pragma unroll
                for (int j = 0; j < 8; j++) acc[i][j] = fmaf(ar[i], br[j], acc[i][j]);
        }
        __syncthreads();
    }

    #pragma unroll
    for (int i = 0; i < 8; i++) {
        int r = brow + tr + i;
        float sc = 1.f;
        if (MODE == 1) {
            int nseg = (r / Tt) % Nn;
            sc = fminf(fmaxf(rs[nseg], 0.f), 1.f);
        }
        #pragma unroll
        for (int g = 0; g < 2; g++) {
            int c = bcol + tc + g * 4;
            float4 o;
            o.x = acc[i][g * 4 + 0]; o.y = acc[i][g * 4 + 1];
            o.z = acc[i][g * 4 + 2]; o.w = acc[i][g * 4 + 3];
            if (MODE == 1) {
                float4 hv = *(const float4*)(hval + (size_t)r * NC + c);
                o.x = hv.x + o.x * sc; o.y = hv.y + o.y * sc;
                o.z = hv.z + o.z * sc; o.w = hv.w + o.w * sc;
            }
            *(float4*)(C + (size_t)r * NC + c) = o;
        }
    }
}

// ---------------- scores + bias + raw softmax + topk softmax ----------------
__global__ void __launch_bounds__(128)
scores_kernel(const float* __restrict__ adj,
              const float* __restrict__ qb, const float* __restrict__ kb) {
    __shared__ float qs[HD];
    __shared__ float ks[Nn][HD + 1];   // pad to kill bank conflicts
    __shared__ float red[Nn];
    __shared__ int   redi[Nn];
    __shared__ float av[Nn];
    __shared__ int   topi[TOPK];

    int i = blockIdx.x, h = blockIdx.y, b = blockIdx.z;
    int tid = threadIdx.x;   // 128 threads, tid == j

    if (tid < HD) qs[tid] = qb[(b * Nn + i) * Dd + h * HD + tid];
    for (int l = tid; l < Nn * HD; l += 128) {
        int j = l >> 6, d = l & 63;
        ks[j][d] = kb[(b * Nn + j) * Dd + h * HD + d];
    }
    __syncthreads();

    float s = 0.f;
    #pragma unroll
    for (int d = 0; d < HD; d++) s = fmaf(qs[d], ks[tid][d], s);
    float bias = logf(fmaxf(adj[(b * Nn + i) * Nn + tid], 1e-12f));
    s = s * SCALE + bias;

    // raw softmax
    red[tid] = s; __syncthreads();
    #pragma unroll
    for (int off = 64; off; off >>= 1) {
        if (tid < off) red[tid] = fmaxf(red[tid], red[tid + off]);
        __syncthreads();
    }
    float m = red[0]; __syncthreads();
    float e = expf(s - m);
    red[tid] = e; __syncthreads();
    #pragma unroll
    for (int off = 64; off; off >>= 1) {
        if (tid < off) red[tid] += red[tid + off];
        __syncthreads();
    }
    float sum1 = red[0]; __syncthreads();
    int rowbase = ((b * Hh + h) * Nn + i) * Nn;
    g_raw[rowbase + tid] = e / sum1;

    // top-16 via 16 argmax rounds (tie -> lower index, matching lax.top_k)
    float wv = s;
    for (int it = 0; it < TOPK; it++) {
        red[tid] = wv; redi[tid] = tid; __syncthreads();
        #pragma unroll
        for (int off = 64; off; off >>= 1) {
            if (tid < off) {
                float ov = red[tid + off]; int oi = redi[tid + off];
                if (ov > red[tid] || (ov == red[tid] && oi < redi[tid])) {
                    red[tid] = ov; redi[tid] = oi;
                }
            }
            __syncthreads();
        }
        int am = redi[0];
        if (tid == 0) topi[it] = am;
        if (tid == am) wv = -INFINITY;
        __syncthreads();
    }

    // masked softmax: kept entries are those removed (wv == -inf)
    float e2 = (wv == -INFINITY) ? expf(s - m) : 0.f;
    red[tid] = e2; __syncthreads();
    #pragma unroll
    for (int off = 64; off; off >>= 1) {
        if (tid < off) red[tid] += red[tid + off];
        __syncthreads();
    }
    float sum2 = red[0];
    float aval = e2 / sum2;
    g_attn[rowbase + tid] = aval;
    av[tid] = aval; __syncthreads();
    if (tid < TOPK) {
        int cbase = ((b * Hh + h) * Nn + i) * TOPK;
        int j = topi[tid];
        g_idx[cbase + tid] = j;
        g_w[cbase + tid]   = av[j];
    }
}

// ---------------- sparse mix: mixed[b,i,t,:] = sum over top-16 j ----------------
__global__ void __launch_bounds__(256)
mixed_kernel(const float* __restrict__ v, float* __restrict__ mixed) {
    __shared__ int   si[Hh][TOPK];
    __shared__ float sw[Hh][TOPK];
    int bi = blockIdx.x;            // b*N + i
    int b = bi / Nn, i = bi % Nn;
    int tid = threadIdx.x;          // 256
    if (tid < Hh * TOPK) {
        int h = tid / TOPK, kk = tid % TOPK;
        int base = ((b * Hh + h) * Nn + i) * TOPK + kk;
        si[h][kk] = g_idx[base];
        sw[h][kk] = g_w[base];
    }
    __syncthreads();
    for (int o = tid; o < Tt * Dd; o += 256) {
        int t = o >> 9, dfull = o & 511;
        int h = dfull >> 6;
        float acc = 0.f;
        #pragma unroll
        for (int kk = 0; kk < TOPK; kk++) {
            int j = si[h][kk];
            acc = fmaf(sw[h][kk], v[((size_t)(b * Nn + j) * Tt + t) * Dd + dfull], acc);
        }
        mixed[((size_t)bi * Tt + t) * Dd + dfull] = acc;
    }
}

// ---------------- head means -> output regions 1 and 2 ----------------
__global__ void means_kernel(float* __restrict__ out_attn, float* __restrict__ out_raw) {
    int idx = blockIdx.x * 256 + threadIdx.x;     // B*N*N
    if (idx >= Bb * Nn * Nn) return;
    int b = idx / (Nn * Nn);
    int rem = idx % (Nn * Nn);
    float sa = 0.f, sr = 0.f;
    #pragma unroll
    for (int h = 0; h < Hh; h++) {
        size_t p = ((size_t)(b * Hh + h)) * Nn * Nn + rem;
        sa += g_attn[p];
        sr += g_raw[p];
    }
    out_attn[idx] = sa * (1.0f / Hh);
    out_raw[idx]  = sr * (1.0f / Hh);
}

// ---------------- launch ----------------
extern "C" void kernel_launch(void* const* d_in, const int* in_sizes, int n_in,
                              void* d_out, int out_size) {
    const float* h_val = (const float*)d_in[0];
    const float* h_map = (const float*)d_in[1];
    const float* adj   = (const float*)d_in[2];
    const float* q_w   = (const float*)d_in[3];
    const float* k_w   = (const float*)d_in[4];
    const float* v_w   = (const float*)d_in[5];
    const float* o_w   = (const float*)d_in[6];
    const float* rs    = (const float*)d_in[7];
    float* out = (float*)d_out;

    float *z, *q, *k, *wtq, *wtk, *wtv, *wto, *v, *mixed;
    cudaGetSymbolAddress((void**)&z,   g_z);
    cudaGetSymbolAddress((void**)&q,   g_q);
    cudaGetSymbolAddress((void**)&k,   g_k);
    cudaGetSymbolAddress((void**)&wtq, g_wtq);
    cudaGetSymbolAddress((void**)&wtk, g_wtk);
    cudaGetSymbolAddress((void**)&wtv, g_wtv);
    cudaGetSymbolAddress((void**)&wto, g_wto);
    cudaGetSymbolAddress((void**)&v,     g_v);
    cudaGetSymbolAddress((void**)&mixed, g_mixed);

    dim3 tb(32, 8), tg(16, 16);
    transpose512<<<tg, tb>>>(q_w, wtq);
    transpose512<<<tg, tb>>>(k_w, wtk);
    transpose512<<<tg, tb>>>(v_w, wtv);
    transpose512<<<tg, tb>>>(o_w, wto);

    zmap_kernel<<<Bb * Nn, Dd>>>(h_map, z);

    // q, k projections: [1024,512] x [512,512]
    sgemm128<0><<<dim3(Dd / 128, (Bb * Nn) / 128), 256>>>(z, wtq, q, Bb * Nn, Dd, Dd, nullptr, nullptr);
    sgemm128<0><<<dim3(Dd / 128, (Bb * Nn) / 128), 256>>>(z, wtk, k, Bb * Nn, Dd, Dd, nullptr, nullptr);

    scores_kernel<<<dim3(Nn, Hh, Bb), 128>>>(adj, q, k);

    // v projection: [65536,512] x [512,512]
    sgemm128<0><<<dim3(Dd / 128, (Bb * Nn * Tt) / 128), 256>>>(h_val, wtv, v, Bb * Nn * Tt, Dd, Dd, nullptr, nullptr);

    mixed_kernel<<<Bb * Nn, 256>>>(v, mixed);

    // output projection with fused residual epilogue
    sgemm128<1><<<dim3(Dd / 128, (Bb * Nn * Tt) / 128), 256>>>(mixed, wto, out, Bb * Nn * Tt, Dd, Dd, h_val, rs);

    means_kernel<<<(Bb * Nn * Nn + 255) / 256, 256>>>(out + OUT0_ELEMS, out + OUT0_ELEMS + MEAN_ELEMS);
}

// round 2
// speedup vs baseline: 2.1095x; 2.1095x over previous
#include <cuda_runtime.h>
#include <cuda_bf16.h>
#include <math.h>
#include <stdint.h>

#define Bb 8
#define Nn 128
#define Tt 64
#define Dd 512
#define Hh 8
#define HD 64
#define TOPK 16
#define SCALE 0.125f   // 1/sqrt(64)

#define OUT0_ELEMS (Bb*Nn*Tt*Dd)        // 33554432
#define MEAN_ELEMS (Bb*Nn*Nn)           // 131072

// ---------------- scratch (static device allocation; no cudaMalloc) ----------------
__device__ float g_z[Bb*Nn*Dd];
__device__ float g_q[Bb*Nn*Dd];
__device__ float g_k[Bb*Nn*Dd];
__device__ float g_wtq[Dd*Dd];
__device__ float g_wtk[Dd*Dd];
__device__ float g_attn[Bb*Hh*Nn*Nn];
__device__ float g_raw[Bb*Hh*Nn*Nn];
__device__ int   g_idx[Bb*Hh*Nn*TOPK];
__device__ float g_w[Bb*Hh*Nn*TOPK];
__device__ __nv_bfloat16 g_v[Bb*Nn*Tt*Dd];       // 64 MB
__device__ __nv_bfloat16 g_mixed[Bb*Nn*Tt*Dd];   // 64 MB

// ---------------- weight transpose (q_w, k_w only) ----------------
__global__ void transpose512(const float* __restrict__ w, float* __restrict__ wt) {
    __shared__ float tile[32][33];
    int bx = blockIdx.x * 32, by = blockIdx.y * 32;
    int tx = threadIdx.x, ty = threadIdx.y;
    #pragma unroll
    for (int i = 0; i < 32; i += 8)
        tile[ty + i][tx] = w[(by + ty + i) * Dd + bx + tx];
    __syncthreads();
    #pragma unroll
    for (int i = 0; i < 32; i += 8)
        wt[(bx + ty + i) * Dd + by + tx] = tile[tx][ty + i];
}

// ---------------- z_map = mean over T ----------------
__global__ void zmap_kernel(const float* __restrict__ hmap, float* __restrict__ z) {
    int bn = blockIdx.x;
    int d  = threadIdx.x;
    const float* p = hmap + (size_t)bn * Tt * Dd + d;
    float s = 0.f;
    #pragma unroll 8
    for (int t = 0; t < Tt; t++) s += p[t * Dd];
    z[bn * Dd + d] = s * (1.0f / Tt);
}

// ---------------- fp32 SGEMM for small q/k projections (unchanged) ----------------
template <int MODE>
__global__ void __launch_bounds__(256)
sgemm128(const float* __restrict__ A, const float* __restrict__ Bm,
         float* __restrict__ C, int M, int NC, int K) {
    __shared__ float As[8][128];
    __shared__ float Bs[8][128];
    int tid  = threadIdx.x;
    int brow = blockIdx.y * 128, bcol = blockIdx.x * 128;
    int tr = (tid / 16) * 8, tc = (tid % 16) * 8;
    int aRow  = tid >> 1, aCol4 = (tid & 1) * 4;
    int bRow  = tid >> 5, bCol4 = (tid & 31) * 4;
    float acc[8][8];
    #pragma unroll
    for (int i = 0; i < 8; i++)
        #pragma unroll
        for (int j = 0; j < 8; j++) acc[i][j] = 0.f;
    for (int k0 = 0; k0 < K; k0 += 8) {
        float4 av = *(const float4*)(A + (size_t)(brow + aRow) * K + k0 + aCol4);
        As[aCol4 + 0][aRow] = av.x; As[aCol4 + 1][aRow] = av.y;
        As[aCol4 + 2][aRow] = av.z; As[aCol4 + 3][aRow] = av.w;
        *(float4*)&Bs[bRow][bCol4] =
            *(const float4*)(Bm + (size_t)(k0 + bRow) * NC + bcol + bCol4);
        __syncthreads();
        #pragma unroll
        for (int kk = 0; kk < 8; kk++) {
            float ar[8], br[8];
            *(float4*)&ar[0] = *(float4*)&As[kk][tr];
            *(float4*)&ar[4] = *(float4*)&As[kk][tr + 4];
            *(float4*)&br[0] = *(float4*)&Bs[kk][tc];
            *(float4*)&br[4] = *(float4*)&Bs[kk][tc + 4];
            #pragma unroll
            for (int i = 0; i < 8; i++)
                #pragma unroll
                for (int j = 0; j < 8; j++) acc[i][j] = fmaf(ar[i], br[j], acc[i][j]);
        }
        __syncthreads();
    }
    #pragma unroll
    for (int i = 0; i < 8; i++) {
        int r = brow + tr + i;
        #pragma unroll
        for (int g = 0; g < 2; g++) {
            int c = bcol + tc + g * 4;
            float4 o;
            o.x = acc[i][g*4+0]; o.y = acc[i][g*4+1];
            o.z = acc[i][g*4+2]; o.w = acc[i][g*4+3];
            *(float4*)(C + (size_t)r * NC + c) = o;
        }
    }
}

// ================== bf16 tensor-core GEMM: C = A[M,512] * W[512,512]^T ==================
// W is the ORIGINAL weight [n][k] row-major (exactly mma.row.col's B layout).
// MODE 0: C (bf16) = acc                (v projection)
// MODE 1: C (f32)  = hval + acc*clamp(rs[(row/T)%N])   (o projection + residual)
__device__ __forceinline__ unsigned pk2(float x, float y) {
    __nv_bfloat162 t = __floats2bfloat162_rn(x, y);
    return *(unsigned*)&t;
}
__device__ __forceinline__ void ldsm4(unsigned& r0, unsigned& r1, unsigned& r2, unsigned& r3,
                                      unsigned addr) {
    asm volatile("ldmatrix.sync.aligned.m8n8.x4.shared.b16 {%0,%1,%2,%3}, [%4];"
                 : "=r"(r0), "=r"(r1), "=r"(r2), "=r"(r3) : "r"(addr));
}
__device__ __forceinline__ void mma16816(float* c, const unsigned* a, const unsigned* b) {
    asm volatile(
        "mma.sync.aligned.m16n8k16.row.col.f32.bf16.bf16.f32 "
        "{%0,%1,%2,%3}, {%4,%5,%6,%7}, {%8,%9}, {%0,%1,%2,%3};"
        : "+f"(c[0]), "+f"(c[1]), "+f"(c[2]), "+f"(c[3])
        : "r"(a[0]), "r"(a[1]), "r"(a[2]), "r"(a[3]), "r"(b[0]), "r"(b[1]));
}

// stage 16 elements (32B as bf16) from gmem into two uint4 of packed bf16
__device__ __forceinline__ void stage16(const float* p, uint4& u0, uint4& u1) {
    float4 f0 = ((const float4*)p)[0], f1 = ((const float4*)p)[1];
    float4 f2 = ((const float4*)p)[2], f3 = ((const float4*)p)[3];
    u0.x = pk2(f0.x, f0.y); u0.y = pk2(f0.z, f0.w);
    u0.z = pk2(f1.x, f1.y); u0.w = pk2(f1.z, f1.w);
    u1.x = pk2(f2.x, f2.y); u1.y = pk2(f2.z, f2.w);
    u1.z = pk2(f3.x, f3.y); u1.w = pk2(f3.z, f3.w);
}
__device__ __forceinline__ void stage16(const __nv_bfloat16* p, uint4& u0, uint4& u1) {
    u0 = ((const uint4*)p)[0]; u1 = ((const uint4*)p)[1];
}

#define ROWB 40          // padded row length in bf16 (80 bytes) -> conflict-free ldmatrix
#define TILEB (128*ROWB) // elements per tile buffer

template <typename AT, int MODE>
__global__ void __launch_bounds__(256)
mma_gemm(const AT* __restrict__ A, const float* __restrict__ W, void* __restrict__ Cv,
         const float* __restrict__ hval, const float* __restrict__ rs) {
    __shared__ __align__(16) __nv_bfloat16 sm[4 * TILEB];  // As[2] then Bs[2], 40960 B
    __nv_bfloat16* As = sm;
    __nv_bfloat16* Bs = sm + 2 * TILEB;

    int tid = threadIdx.x;
    int lane = tid & 31, wid = tid >> 5;
    int wm = wid >> 2, wn = wid & 3;           // 2 x 4 warp grid, warp tile 64x32
    int brow = blockIdx.y * 128, bcol = blockIdx.x * 128;

    // gmem staging: thread -> (row = tid/2, halfK = tid&1)
    int srow = tid >> 1, shalf = (tid & 1) * 16;
    const AT*    aptr = A + (size_t)(brow + srow) * 512 + shalf;
    const float* bptr = W + (size_t)(bcol + srow) * 512 + shalf;
    __nv_bfloat16* aSt = As + srow * ROWB + shalf;
    __nv_bfloat16* bSt = Bs + srow * ROWB + shalf;

    unsigned sA = (unsigned)__cvta_generic_to_shared(As);
    unsigned sB = (unsigned)__cvta_generic_to_shared(Bs);
    // ldmatrix thread-address components
    unsigned aAddr = sA + (unsigned)((wm * 64 + (lane & 15)) * 80 + ((lane >> 4) << 4));
    unsigned bAddr = sB + (unsigned)((wn * 32 + ((lane >> 3) & 1) * 8 + (lane & 7)) * 80
                                     + ((lane >> 4) << 4));

    float acc[4][4][4];
    #pragma unroll
    for (int i = 0; i < 4; i++)
        #pragma unroll
        for (int j = 0; j < 4; j++)
            #pragma unroll
            for (int e = 0; e < 4; e++) acc[i][j][e] = 0.f;

    uint4 ua0, ua1, ub0, ub1;
    stage16(aptr, ua0, ua1);
    stage16(bptr, ub0, ub1);
    ((uint4*)aSt)[0] = ua0; ((uint4*)(aSt + 8))[0] = ua1;
    ((uint4*)bSt)[0] = ub0; ((uint4*)(bSt + 8))[0] = ub1;
    __syncthreads();

    int buf = 0;
    #pragma unroll 1
    for (int it = 0; it < 16; it++) {
        if (it < 15) {
            stage16(aptr + (it + 1) * 32, ua0, ua1);
            stage16(bptr + (it + 1) * 32, ub0, ub1);
        }
        unsigned abase = aAddr + buf * (TILEB * 2);
        unsigned bbase = bAddr + buf * (TILEB * 2);
        #pragma unroll
        for (int ks = 0; ks < 2; ks++) {
            unsigned a[4][4], b[4][2];
            #pragma unroll
            for (int mi = 0; mi < 4; mi++)
                ldsm4(a[mi][0], a[mi][1], a[mi][2], a[mi][3],
                      abase + mi * (16 * 80) + ks * 32);
            #pragma unroll
            for (int pr = 0; pr < 2; pr++)
                ldsm4(b[2*pr][0], b[2*pr+1][0], b[2*pr][1], b[2*pr+1][1],
                      bbase + pr * (16 * 80) + ks * 32);
            #pragma unroll
            for (int mi = 0; mi < 4; mi++)
                #pragma unroll
                for (int ni = 0; ni < 4; ni++)
                    mma16816(acc[mi][ni], a[mi], b[ni]);
        }
        if (it < 15) {
            __nv_bfloat16* aD = aSt + (buf ^ 1) * TILEB;
            __nv_bfloat16* bD = bSt + (buf ^ 1) * TILEB;
            ((uint4*)aD)[0] = ua0; ((uint4*)(aD + 8))[0] = ua1;
            ((uint4*)bD)[0] = ub0; ((uint4*)(bD + 8))[0] = ub1;
        }
        __syncthreads();
        buf ^= 1;
    }

    // epilogue
    #pragma unroll
    for (int mi = 0; mi < 4; mi++) {
        int r0 = brow + wm * 64 + mi * 16 + (lane >> 2);
        #pragma unroll
        for (int half = 0; half < 2; half++) {
            int r = r0 + half * 8;
            float sc = 1.f;
            if (MODE == 1) {
                int nseg = (r / Tt) % Nn;
                sc = fminf(fmaxf(rs[nseg], 0.f), 1.f);
            }
            #pragma unroll
            for (int ni = 0; ni < 4; ni++) {
                int c = bcol + wn * 32 + ni * 8 + (lane & 3) * 2;
                float x = acc[mi][ni][half * 2 + 0];
                float y = acc[mi][ni][half * 2 + 1];
                if (MODE == 0) {
                    *(__nv_bfloat162*)((__nv_bfloat16*)Cv + (size_t)r * 512 + c) =
                        __floats2bfloat162_rn(x, y);
                } else {
                    const float2 hv = *(const float2*)(hval + (size_t)r * 512 + c);
                    float2 o; o.x = hv.x + x * sc; o.y = hv.y + y * sc;
                    *(float2*)((float*)Cv + (size_t)r * 512 + c) = o;
                }
            }
        }
    }
}

// ---------------- scores + bias + raw softmax + topk softmax ----------------
__global__ void __launch_bounds__(128)
scores_kernel(const float* __restrict__ adj,
              const float* __restrict__ qb, const float* __restrict__ kb) {
    __shared__ float qs[HD];
    __shared__ float ks[Nn][HD + 1];
    __shared__ float red[Nn];
    __shared__ int   redi[Nn];
    __shared__ float av[Nn];
    __shared__ int   topi[TOPK];

    int i = blockIdx.x, h = blockIdx.y, b = blockIdx.z;
    int tid = threadIdx.x;

    if (tid < HD) qs[tid] = qb[(b * Nn + i) * Dd + h * HD + tid];
    for (int l = tid; l < Nn * HD; l += 128) {
        int j = l >> 6, d = l & 63;
        ks[j][d] = kb[(b * Nn + j) * Dd + h * HD + d];
    }
    __syncthreads();

    float s = 0.f;
    #pragma unroll
    for (int d = 0; d < HD; d++) s = fmaf(qs[d], ks[tid][d], s);
    float bias = logf(fmaxf(adj[(b * Nn + i) * Nn + tid], 1e-12f));
    s = s * SCALE + bias;

    red[tid] = s; __syncthreads();
    #pragma unroll
    for (int off = 64; off; off >>= 1) {
        if (tid < off) red[tid] = fmaxf(red[tid], red[tid + off]);
        __syncthreads();
    }
    float m = red[0]; __syncthreads();
    float e = expf(s - m);
    red[tid] = e; __syncthreads();
    #pragma unroll
    for (int off = 64; off; off >>= 1) {
        if (tid < off) red[tid] += red[tid + off];
        __syncthreads();
    }
    float sum1 = red[0]; __syncthreads();
    int rowbase = ((b * Hh + h) * Nn + i) * Nn;
    g_raw[rowbase + tid] = e / sum1;

    float wv = s;
    for (int it = 0; it < TOPK; it++) {
        red[tid] = wv; redi[tid] = tid; __syncthreads();
        #pragma unroll
        for (int off = 64; off; off >>= 1) {
            if (tid < off) {
                float ov = red[tid + off]; int oi = redi[tid + off];
                if (ov > red[tid] || (ov == red[tid] && oi < redi[tid])) {
                    red[tid] = ov; redi[tid] = oi;
                }
            }
            __syncthreads();
        }
        int am = redi[0];
        if (tid == 0) topi[it] = am;
        if (tid == am) wv = -INFINITY;
        __syncthreads();
    }

    float e2 = (wv == -INFINITY) ? expf(s - m) : 0.f;
    red[tid] = e2; __syncthreads();
    #pragma unroll
    for (int off = 64; off; off >>= 1) {
        if (tid < off) red[tid] += red[tid + off];
        __syncthreads();
    }
    float sum2 = red[0];
    float aval = e2 / sum2;
    g_attn[rowbase + tid] = aval;
    av[tid] = aval; __syncthreads();
    if (tid < TOPK) {
        int cbase = ((b * Hh + h) * Nn + i) * TOPK;
        int j = topi[tid];
        g_idx[cbase + tid] = j;
        g_w[cbase + tid]   = av[j];
    }
}

// ---------------- sparse mix (bf16 in/out) ----------------
__global__ void __launch_bounds__(256)
mixed_kernel(const __nv_bfloat16* __restrict__ v, __nv_bfloat16* __restrict__ mixed) {
    __shared__ int   si[Hh][TOPK];
    __shared__ float sw[Hh][TOPK];
    int bi = blockIdx.x;
    int b = bi / Nn, i = bi % Nn;
    int tid = threadIdx.x;
    if (tid < Hh * TOPK) {
        int h = tid / TOPK, kk = tid % TOPK;
        int base = ((b * Hh + h) * Nn + i) * TOPK + kk;
        si[h][kk] = g_idx[base];
        sw[h][kk] = g_w[base];
    }
    __syncthreads();
    const int HALFE = Tt * Dd / 2;   // 16384 bf162 elems
    for (int o = tid; o < HALFE; o += 256) {
        int t = o >> 8;            // /256
        int d2 = o & 255;
        int h = d2 >> 5;           // (d2*2)/64
        float ax = 0.f, ay = 0.f;
        #pragma unroll
        for (int kk = 0; kk < TOPK; kk++) {
            int j = si[h][kk];
            __nv_bfloat162 vv = *(const __nv_bfloat162*)(
                v + (((size_t)(b * Nn + j) * Tt + t) << 9) + d2 * 2);
            float2 f = __bfloat1622float2(vv);
            float w = sw[h][kk];
            ax = fmaf(w, f.x, ax); ay = fmaf(w, f.y, ay);
        }
        *(__nv_bfloat162*)(mixed + (((size_t)bi * Tt + t) << 9) + d2 * 2) =
            __floats2bfloat162_rn(ax, ay);
    }
}

// ---------------- head means ----------------
__global__ void means_kernel(float* __restrict__ out_attn, float* __restrict__ out_raw) {
    int idx = blockIdx.x * 256 + threadIdx.x;
    if (idx >= Bb * Nn * Nn) return;
    int b = idx / (Nn * Nn);
    int rem = idx % (Nn * Nn);
    float sa = 0.f, sr = 0.f;
    #pragma unroll
    for (int h = 0; h < Hh; h++) {
        size_t p = ((size_t)(b * Hh + h)) * Nn * Nn + rem;
        sa += g_attn[p];
        sr += g_raw[p];
    }
    out_attn[idx] = sa * (1.0f / Hh);
    out_raw[idx]  = sr * (1.0f / Hh);
}

// ---------------- launch ----------------
extern "C" void kernel_launch(void* const* d_in, const int* in_sizes, int n_in,
                              void* d_out, int out_size) {
    const float* h_val = (const float*)d_in[0];
    const float* h_map = (const float*)d_in[1];
    const float* adj   = (const float*)d_in[2];
    const float* q_w   = (const float*)d_in[3];
    const float* k_w   = (const float*)d_in[4];
    const float* v_w   = (const float*)d_in[5];
    const float* o_w   = (const float*)d_in[6];
    const float* rs    = (const float*)d_in[7];
    float* out = (float*)d_out;

    float *z, *q, *k, *wtq, *wtk;
    __nv_bfloat16 *v, *mixed;
    cudaGetSymbolAddress((void**)&z,   g_z);
    cudaGetSymbolAddress((void**)&q,   g_q);
    cudaGetSymbolAddress((void**)&k,   g_k);
    cudaGetSymbolAddress((void**)&wtq, g_wtq);
    cudaGetSymbolAddress((void**)&wtk, g_wtk);
    cudaGetSymbolAddress((void**)&v,     g_v);
    cudaGetSymbolAddress((void**)&mixed, g_mixed);

    dim3 tb(32, 8), tg(16, 16);
    transpose512<<<tg, tb>>>(q_w, wtq);
    transpose512<<<tg, tb>>>(k_w, wtk);

    zmap_kernel<<<Bb * Nn, Dd>>>(h_map, z);

    sgemm128<0><<<dim3(Dd / 128, (Bb * Nn) / 128), 256>>>(z, wtq, q, Bb * Nn, Dd, Dd);
    sgemm128<0><<<dim3(Dd / 128, (Bb * Nn) / 128), 256>>>(z, wtk, k, Bb * Nn, Dd, Dd);

    scores_kernel<<<dim3(Nn, Hh, Bb), 128>>>(adj, q, k);

    // v = h_val @ v_w^T   (bf16 tensor cores, weight used untransposed)
    mma_gemm<float, 0><<<dim3(4, 512), 256>>>(h_val, v_w, (void*)v, nullptr, nullptr);

    mixed_kernel<<<Bb * Nn, 256>>>(v, mixed);

    // out = h_val + (mixed @ o_w^T) * clamp(rs)
    mma_gemm<__nv_bfloat16, 1><<<dim3(4, 512), 256>>>(mixed, o_w, (void*)out, h_val, rs);

    means_kernel<<<(Bb * Nn * Nn + 255) / 256, 256>>>(out + OUT0_ELEMS, out + OUT0_ELEMS + MEAN_ELEMS);
}

// round 3
// speedup vs baseline: 3.4543x; 1.6375x over previous
#include <cuda_runtime.h>
#include <cuda_bf16.h>
#include <math.h>
#include <stdint.h>

#define Bb 8
#define Nn 128
#define Tt 64
#define Dd 512
#define Hh 8
#define HD 64
#define TOPK 16
#define SCALE 0.125f

#define OUT0_ELEMS (Bb*Nn*Tt*Dd)
#define MEAN_ELEMS (Bb*Nn*Nn)

typedef __nv_bfloat16 bf16;

// ---------------- static device scratch ----------------
__device__ float g_z[Bb*Nn*Dd];
__device__ float g_q[Bb*Nn*Dd];
__device__ float g_k[Bb*Nn*Dd];
__device__ float g_attn[Bb*Hh*Nn*Nn];
__device__ float g_raw[Bb*Hh*Nn*Nn];
__device__ int   g_idx[Bb*Hh*Nn*TOPK];
__device__ bf16  g_hvb[Bb*Nn*Tt*Dd];     // h_val in bf16 (64 MB)
__device__ bf16  g_vwb[Dd*Dd];
__device__ bf16  g_owb[Dd*Dd];
__device__ bf16  g_v[Bb*Nn*Tt*Dd];       // 64 MB
__device__ bf16  g_mixed[Bb*Nn*Tt*Dd];   // 64 MB

// ---------------- fp32 -> bf16 convert ----------------
__global__ void f2bf(const float4* __restrict__ x, uint2* __restrict__ y, int n4) {
    int i = blockIdx.x * 256 + threadIdx.x;
    if (i >= n4) return;
    float4 f = x[i];
    __nv_bfloat162 a = __floats2bfloat162_rn(f.x, f.y);
    __nv_bfloat162 b = __floats2bfloat162_rn(f.z, f.w);
    uint2 u; u.x = *(unsigned*)&a; u.y = *(unsigned*)&b;
    y[i] = u;
}

// ---------------- z_map = mean over T ----------------
__global__ void zmap_kernel(const float* __restrict__ hmap) {
    int bn = blockIdx.x;
    int d  = threadIdx.x;
    const float* p = hmap + (size_t)bn * Tt * Dd + d;
    float s = 0.f;
    #pragma unroll 8
    for (int t = 0; t < Tt; t++) s += p[t * Dd];
    g_z[bn * Dd + d] = s * (1.0f / Tt);
}

// ---------------- fused q/k projection: 64x64 tiles, weight untransposed ----------------
// C[m,n] = sum_k z[m,k] * w[n,k];  blockIdx.x<8 -> q_w -> g_q, else k_w -> g_k
__global__ void __launch_bounds__(256)
qk_gemm(const float* __restrict__ qw, const float* __restrict__ kw) {
    __shared__ float As[32][72];
    __shared__ float Bs[32][72];
    int bx = blockIdx.x, by = blockIdx.y;
    const float* wsrc = (bx < 8) ? qw : kw;
    float* outp = (bx < 8) ? g_q : g_k;
    int ncol0 = (bx & 7) * 64, bm = by * 64;
    int tid = threadIdx.x;
    int tm = tid >> 4, tn = tid & 15;
    float acc[4][4];
    #pragma unroll
    for (int i = 0; i < 4; i++)
        #pragma unroll
        for (int j = 0; j < 4; j++) acc[i][j] = 0.f;

    for (int k0 = 0; k0 < 512; k0 += 32) {
        #pragma unroll
        for (int it = 0; it < 2; it++) {
            int idx = tid + it * 256;
            int r = idx >> 3, c4 = (idx & 7) * 4;
            float4 v = *(const float4*)(g_z + (size_t)(bm + r) * 512 + k0 + c4);
            As[c4+0][r] = v.x; As[c4+1][r] = v.y; As[c4+2][r] = v.z; As[c4+3][r] = v.w;
            float4 u = *(const float4*)(wsrc + (size_t)(ncol0 + r) * 512 + k0 + c4);
            Bs[c4+0][r] = u.x; Bs[c4+1][r] = u.y; Bs[c4+2][r] = u.z; Bs[c4+3][r] = u.w;
        }
        __syncthreads();
        #pragma unroll
        for (int kk = 0; kk < 32; kk++) {
            float4 a = *(const float4*)&As[kk][tm * 4];
            float4 b = *(const float4*)&Bs[kk][tn * 4];
            float ar[4] = {a.x, a.y, a.z, a.w};
            float br[4] = {b.x, b.y, b.z, b.w};
            #pragma unroll
            for (int i = 0; i < 4; i++)
                #pragma unroll
                for (int j = 0; j < 4; j++) acc[i][j] = fmaf(ar[i], br[j], acc[i][j]);
        }
        __syncthreads();
    }
    #pragma unroll
    for (int e = 0; e < 4; e++) {
        float4 o; o.x = acc[e][0]; o.y = acc[e][1]; o.z = acc[e][2]; o.w = acc[e][3];
        *(float4*)(outp + (size_t)(bm + tm * 4 + e) * 512 + ncol0 + tn * 4) = o;
    }
}

// ---------------- scores: warp-per-row, REDUX top-k ----------------
__device__ __forceinline__ unsigned fenc(float v) {
    int b = __float_as_int(v);
    return (b >= 0) ? ((unsigned)b | 0x80000000u) : ~(unsigned)b;
}
__device__ __forceinline__ float wmax(float v) {
    #pragma unroll
    for (int o = 16; o; o >>= 1) v = fmaxf(v, __shfl_xor_sync(0xffffffffu, v, o));
    return v;
}
__device__ __forceinline__ float wsum(float v) {
    #pragma unroll
    for (int o = 16; o; o >>= 1) v += __shfl_xor_sync(0xffffffffu, v, o);
    return v;
}

__global__ void __launch_bounds__(256)
scores2(const float* __restrict__ adj) {
    __shared__ float ks[64][128];
    int ih = blockIdx.x, h = blockIdx.y, b = blockIdx.z;
    int tid = threadIdx.x, lane = tid & 31, w = tid >> 5;

    {   // stage k-slice transposed: ks[d][j]
        int j = tid >> 1, dh = (tid & 1) * 32;
        const float* kp = g_k + (size_t)(b * 128 + j) * 512 + h * 64 + dh;
        #pragma unroll
        for (int f = 0; f < 8; f++) {
            float4 v = *(const float4*)(kp + f * 4);
            ks[dh + f*4 + 0][j] = v.x; ks[dh + f*4 + 1][j] = v.y;
            ks[dh + f*4 + 2][j] = v.z; ks[dh + f*4 + 3][j] = v.w;
        }
    }
    __syncthreads();

    for (int r = 0; r < 8; r++) {
        int i = ih * 64 + w * 8 + r;
        float2 qr = *(const float2*)(g_q + (size_t)(b * 128 + i) * 512 + h * 64 + lane * 2);
        float a0 = 0.f, a1 = 0.f, a2 = 0.f, a3 = 0.f;
        #pragma unroll
        for (int d = 0; d < 64; d++) {
            float qd = __shfl_sync(0xffffffffu, (d & 1) ? qr.y : qr.x, d >> 1);
            float4 kv = *(const float4*)&ks[d][lane * 4];
            a0 = fmaf(qd, kv.x, a0); a1 = fmaf(qd, kv.y, a1);
            a2 = fmaf(qd, kv.z, a2); a3 = fmaf(qd, kv.w, a3);
        }
        float4 adjv = *(const float4*)(adj + (size_t)(b * 128 + i) * 128 + lane * 4);
        float s4[4];
        s4[0] = a0 * SCALE + logf(fmaxf(adjv.x, 1e-12f));
        s4[1] = a1 * SCALE + logf(fmaxf(adjv.y, 1e-12f));
        s4[2] = a2 * SCALE + logf(fmaxf(adjv.z, 1e-12f));
        s4[3] = a3 * SCALE + logf(fmaxf(adjv.w, 1e-12f));

        float m = wmax(fmaxf(fmaxf(s4[0], s4[1]), fmaxf(s4[2], s4[3])));
        float e4[4];
        #pragma unroll
        for (int q = 0; q < 4; q++) e4[q] = expf(s4[q] - m);
        float sum1 = wsum(e4[0] + e4[1] + e4[2] + e4[3]);

        size_t rb = ((size_t)(b * 8 + h) * 128 + i) * 128;
        float4 rv; rv.x = e4[0]/sum1; rv.y = e4[1]/sum1; rv.z = e4[2]/sum1; rv.w = e4[3]/sum1;
        *(float4*)(g_raw + rb + lane * 4) = rv;

        unsigned u4[4];
        #pragma unroll
        for (int q = 0; q < 4; q++) u4[q] = fenc(s4[q]);
        int myj = 0;
        for (int itk = 0; itk < TOPK; itk++) {
            unsigned ub = u4[0]; int jb = lane * 4;
            #pragma unroll
            for (int q = 1; q < 4; q++)
                if (u4[q] > ub) { ub = u4[q]; jb = lane * 4 + q; }
            unsigned gm = __reduce_max_sync(0xffffffffu, ub);
            unsigned jm = (ub == gm) ? (unsigned)jb : 0xFFFFu;
            unsigned js = __reduce_min_sync(0xffffffffu, jm);
            if (lane == itk) myj = (int)js;
            if ((js >> 2) == (unsigned)lane) u4[js & 3] = 0u;
        }
        float es = 0.f;
        #pragma unroll
        for (int q = 0; q < 4; q++) if (u4[q] == 0u) es += e4[q];
        float sum2 = wsum(es);
        float4 av;
        av.x = (u4[0] == 0u) ? e4[0]/sum2 : 0.f;
        av.y = (u4[1] == 0u) ? e4[1]/sum2 : 0.f;
        av.z = (u4[2] == 0u) ? e4[2]/sum2 : 0.f;
        av.w = (u4[3] == 0u) ? e4[3]/sum2 : 0.f;
        *(float4*)(g_attn + rb + lane * 4) = av;
        if (lane < TOPK)
            g_idx[((size_t)(b * 8 + h) * 128 + i) * TOPK + lane] = myj;
    }
}

// ---------------- bf16 tensor GEMM with cp.async 3-stage ----------------
__device__ __forceinline__ void cp16(void* smem, const void* g) {
    unsigned s = (unsigned)__cvta_generic_to_shared(smem);
    asm volatile("cp.async.cg.shared.global [%0], [%1], 16;" :: "r"(s), "l"(g));
}
__device__ __forceinline__ void ldsm4(unsigned& r0, unsigned& r1, unsigned& r2, unsigned& r3,
                                      unsigned addr) {
    asm volatile("ldmatrix.sync.aligned.m8n8.x4.shared.b16 {%0,%1,%2,%3}, [%4];"
                 : "=r"(r0), "=r"(r1), "=r"(r2), "=r"(r3) : "r"(addr));
}
__device__ __forceinline__ void mma16816(float* c, const unsigned* a, const unsigned* b) {
    asm volatile(
        "mma.sync.aligned.m16n8k16.row.col.f32.bf16.bf16.f32 "
        "{%0,%1,%2,%3}, {%4,%5,%6,%7}, {%8,%9}, {%0,%1,%2,%3};"
        : "+f"(c[0]), "+f"(c[1]), "+f"(c[2]), "+f"(c[3])
        : "r"(a[0]), "r"(a[1]), "r"(a[2]), "r"(a[3]), "r"(b[0]), "r"(b[1]));
}

#define STAGE_B 20480   // A tile 128*80B + B tile 128*80B

template <int MODE>
__global__ void __launch_bounds__(256)
mma_gemm3(const bf16* __restrict__ A, const bf16* __restrict__ W, void* __restrict__ Cv,
          const float* __restrict__ hval, const float* __restrict__ rs) {
    extern __shared__ __align__(16) char dynsm[];
    int tid = threadIdx.x;
    int lane = tid & 31, wid = tid >> 5;
    int wm = wid >> 2, wn = wid & 3;
    int brow = blockIdx.y * 128, bcol = blockIdx.x * 128;

    const bf16* asrc = (tid < 128) ? (A + (size_t)(brow + tid) * 512)
                                   : (W + (size_t)(bcol + tid - 128) * 512);
    char* sdst0 = dynsm + ((tid < 128) ? tid * 80 : (10240 + (tid - 128) * 80));

    unsigned smBase = (unsigned)__cvta_generic_to_shared(dynsm);
    unsigned aOff = (unsigned)((wm * 64 + (lane & 15)) * 80 + ((lane >> 4) << 4));
    unsigned bOff = (unsigned)(10240 + (wn * 32 + ((lane >> 3) & 1) * 8 + (lane & 7)) * 80
                               + ((lane >> 4) << 4));

    float acc[4][4][4];
    #pragma unroll
    for (int i = 0; i < 4; i++)
        #pragma unroll
        for (int j = 0; j < 4; j++)
            #pragma unroll
            for (int e = 0; e < 4; e++) acc[i][j][e] = 0.f;

    // prologue: stages 0,1
    #pragma unroll
    for (int s = 0; s < 2; s++) {
        char* dst = sdst0 + s * STAGE_B;
        const bf16* src = asrc + s * 32;
        #pragma unroll
        for (int c = 0; c < 4; c++) cp16(dst + c * 16, src + c * 8);
        asm volatile("cp.async.commit_group;");
    }

    #pragma unroll 1
    for (int it = 0; it < 16; it++) {
        if (it < 14) asm volatile("cp.async.wait_group 1;");
        else         asm volatile("cp.async.wait_group 0;");
        __syncthreads();
        if (it + 2 < 16) {
            int s = it + 2;
            char* dst = sdst0 + (s % 3) * STAGE_B;
            const bf16* src = asrc + s * 32;
            #pragma unroll
            for (int c = 0; c < 4; c++) cp16(dst + c * 16, src + c * 8);
            asm volatile("cp.async.commit_group;");
        }
        unsigned base = smBase + (unsigned)((it % 3) * STAGE_B);
        #pragma unroll
        for (int ks = 0; ks < 2; ks++) {
            unsigned a[4][4], b[4][2];
            #pragma unroll
            for (int mi = 0; mi < 4; mi++)
                ldsm4(a[mi][0], a[mi][1], a[mi][2], a[mi][3],
                      base + aOff + mi * (16 * 80) + ks * 32);
            #pragma unroll
            for (int pr = 0; pr < 2; pr++)
                ldsm4(b[2*pr][0], b[2*pr+1][0], b[2*pr][1], b[2*pr+1][1],
                      base + bOff + pr * (16 * 80) + ks * 32);
            #pragma unroll
            for (int mi = 0; mi < 4; mi++)
                #pragma unroll
                for (int ni = 0; ni < 4; ni++)
                    mma16816(acc[mi][ni], a[mi], b[ni]);
        }
    }

    #pragma unroll
    for (int mi = 0; mi < 4; mi++) {
        int r0 = brow + wm * 64 + mi * 16 + (lane >> 2);
        #pragma unroll
        for (int half = 0; half < 2; half++) {
            int r = r0 + half * 8;
            float sc = 1.f;
            if (MODE == 1) {
                int nseg = (r / Tt) % Nn;
                sc = fminf(fmaxf(rs[nseg], 0.f), 1.f);
            }
            #pragma unroll
            for (int ni = 0; ni < 4; ni++) {
                int c = bcol + wn * 32 + ni * 8 + (lane & 3) * 2;
                float x = acc[mi][ni][half * 2 + 0];
                float y = acc[mi][ni][half * 2 + 1];
                if (MODE == 0) {
                    *(__nv_bfloat162*)((bf16*)Cv + (size_t)r * 512 + c) =
                        __floats2bfloat162_rn(x, y);
                } else {
                    const float2 hv = *(const float2*)(hval + (size_t)r * 512 + c);
                    float2 o; o.x = hv.x + x * sc; o.y = hv.y + y * sc;
                    *(float2*)((float*)Cv + (size_t)r * 512 + c) = o;
                }
            }
        }
    }
}

// ---------------- mixed: smem-tiled sparse mix ----------------
__global__ void __launch_bounds__(256)
mixed2(const bf16* __restrict__ v, bf16* __restrict__ mixed) {
    __shared__ bf16 sv[128][128];
    __shared__ unsigned char su[128][16];
    __shared__ float swt[128][16];
    int nt = blockIdx.x, h = blockIdx.y, b = blockIdx.z;
    int tid = threadIdx.x, lane = tid & 31, w = tid >> 5;

    {   // stage v chunk [128 j][128 n], n = tt*64 + d
        int j = tid >> 1, tt = tid & 1;
        const uint4* src = (const uint4*)(v + ((size_t)(b * 128 + j) * 64 + nt * 2 + tt) * 512
                                            + h * 64);
        uint4* dst = (uint4*)&sv[j][tt * 64];
        #pragma unroll
        for (int c = 0; c < 8; c++) dst[c] = src[c];
    }
    {   // stage topk idx + weights (weights read from dense attn)
        int base = (b * 8 + h) * 128;
        #pragma unroll
        for (int e = tid * 8; e < tid * 8 + 8; e++) {
            int i = e >> 4, kk = e & 15;
            int j = g_idx[(size_t)(base + i) * 16 + kk];
            su[i][kk] = (unsigned char)j;
            swt[i][kk] = g_attn[(size_t)(base + i) * 128 + j];
        }
    }
    __syncthreads();

    int tt = lane >> 4, d = (lane & 15) * 4;
    for (int r = 0; r < 16; r++) {
        int i = w * 16 + r;
        float a0 = 0.f, a1 = 0.f, a2 = 0.f, a3 = 0.f;
        #pragma unroll
        for (int kk = 0; kk < 16; kk++) {
            int j = su[i][kk];
            float wt = swt[i][kk];
            uint2 vv = *(const uint2*)&sv[j][lane * 4];
            float2 f0 = __bfloat1622float2(*(__nv_bfloat162*)&vv.x);
            float2 f1 = __bfloat1622float2(*(__nv_bfloat162*)&vv.y);
            a0 = fmaf(wt, f0.x, a0); a1 = fmaf(wt, f0.y, a1);
            a2 = fmaf(wt, f1.x, a2); a3 = fmaf(wt, f1.y, a3);
        }
        __nv_bfloat162 o0 = __floats2bfloat162_rn(a0, a1);
        __nv_bfloat162 o1 = __floats2bfloat162_rn(a2, a3);
        uint2 ov; ov.x = *(unsigned*)&o0; ov.y = *(unsigned*)&o1;
        *(uint2*)(mixed + ((size_t)(b * 128 + i) * 64 + nt * 2 + tt) * 512 + h * 64 + d) = ov;
    }
}

// ---------------- head means ----------------
__global__ void means_kernel(float* __restrict__ out_attn, float* __restrict__ out_raw) {
    int idx = blockIdx.x * 256 + threadIdx.x;
    if (idx >= Bb * Nn * Nn) return;
    int b = idx / (Nn * Nn);
    int rem = idx % (Nn * Nn);
    float sa = 0.f, sr = 0.f;
    #pragma unroll
    for (int h = 0; h < Hh; h++) {
        size_t p = ((size_t)(b * Hh + h)) * Nn * Nn + rem;
        sa += g_attn[p];
        sr += g_raw[p];
    }
    out_attn[idx] = sa * (1.0f / Hh);
    out_raw[idx]  = sr * (1.0f / Hh);
}

// ---------------- launch ----------------
extern "C" void kernel_launch(void* const* d_in, const int* in_sizes, int n_in,
                              void* d_out, int out_size) {
    const float* h_val = (const float*)d_in[0];
    const float* h_map = (const float*)d_in[1];
    const float* adj   = (const float*)d_in[2];
    const float* q_w   = (const float*)d_in[3];
    const float* k_w   = (const float*)d_in[4];
    const float* v_w   = (const float*)d_in[5];
    const float* o_w   = (const float*)d_in[6];
    const float* rs    = (const float*)d_in[7];
    float* out = (float*)d_out;

    bf16 *hvb, *vwb, *owb, *v, *mixed;
    cudaGetSymbolAddress((void**)&hvb,   g_hvb);
    cudaGetSymbolAddress((void**)&vwb,   g_vwb);
    cudaGetSymbolAddress((void**)&owb,   g_owb);
    cudaGetSymbolAddress((void**)&v,     g_v);
    cudaGetSymbolAddress((void**)&mixed, g_mixed);

    cudaFuncSetAttribute(mma_gemm3<0>, cudaFuncAttributeMaxDynamicSharedMemorySize, 3 * STAGE_B);
    cudaFuncSetAttribute(mma_gemm3<1>, cudaFuncAttributeMaxDynamicSharedMemorySize, 3 * STAGE_B);

    f2bf<<<(OUT0_ELEMS/4 + 255)/256, 256>>>((const float4*)h_val, (uint2*)hvb, OUT0_ELEMS/4);
    f2bf<<<(Dd*Dd/4 + 255)/256, 256>>>((const float4*)v_w, (uint2*)vwb, Dd*Dd/4);
    f2bf<<<(Dd*Dd/4 + 255)/256, 256>>>((const float4*)o_w, (uint2*)owb, Dd*Dd/4);

    zmap_kernel<<<Bb * Nn, Dd>>>(h_map);
    qk_gemm<<<dim3(16, 16), 256>>>(q_w, k_w);
    scores2<<<dim3(2, Hh, Bb), 256>>>(adj);

    mma_gemm3<0><<<dim3(4, 512), 256, 3 * STAGE_B>>>(hvb, vwb, (void*)v, nullptr, nullptr);
    mixed2<<<dim3(32, Hh, Bb), 256>>>(v, mixed);
    mma_gemm3<1><<<dim3(4, 512), 256, 3 * STAGE_B>>>(mixed, owb, (void*)out, h_val, rs);

    means_kernel<<<(MEAN_ELEMS + 255)/256, 256>>>(out + OUT0_ELEMS, out + OUT0_ELEMS + MEAN_ELEMS);
}

// round 4
// speedup vs baseline: 3.4575x; 1.0009x over previous
#include <cuda_runtime.h>
#include <cuda_bf16.h>
#include <math.h>
#include <stdint.h>

#define Bb 8
#define Nn 128
#define Tt 64
#define Dd 512
#define Hh 8
#define HD 64
#define TOPK 16
#define SCALE 0.125f

#define OUT0_ELEMS (Bb*Nn*Tt*Dd)
#define MEAN_ELEMS (Bb*Nn*Nn)

typedef __nv_bfloat16 bf16;

// ---------------- static device scratch ----------------
__device__ float g_z[Bb*Nn*Dd];
__device__ float g_q[Bb*Nn*Dd];
__device__ float g_k[Bb*Nn*Dd];
__device__ float g_attn[Bb*Hh*Nn*Nn];
__device__ float g_raw[Bb*Hh*Nn*Nn];
__device__ int   g_idx[Bb*Hh*Nn*TOPK];
__device__ bf16  g_hvb[Bb*Nn*Tt*Dd];     // h_val in bf16 (64 MB)
__device__ bf16  g_vwb[Dd*Dd];
__device__ bf16  g_owb[Dd*Dd];
__device__ bf16  g_v[Bb*Nn*Tt*Dd];       // 64 MB
__device__ bf16  g_mixed[Bb*Nn*Tt*Dd];   // 64 MB

// ---------------- fp32 -> bf16 convert ----------------
__global__ void f2bf(const float4* __restrict__ x, uint2* __restrict__ y, int n4) {
    int i = blockIdx.x * 256 + threadIdx.x;
    if (i >= n4) return;
    float4 f = x[i];
    __nv_bfloat162 a = __floats2bfloat162_rn(f.x, f.y);
    __nv_bfloat162 b = __floats2bfloat162_rn(f.z, f.w);
    uint2 u; u.x = *(unsigned*)&a; u.y = *(unsigned*)&b;
    y[i] = u;
}

// ---------------- z_map = mean over T ----------------
__global__ void zmap_kernel(const float* __restrict__ hmap) {
    int bn = blockIdx.x;
    int d  = threadIdx.x;
    const float* p = hmap + (size_t)bn * Tt * Dd + d;
    float s = 0.f;
    #pragma unroll 8
    for (int t = 0; t < Tt; t++) s += p[t * Dd];
    g_z[bn * Dd + d] = s * (1.0f / Tt);
}

// ---------------- fused q/k projection: 64x64 tiles, weight untransposed ----------------
// C[m,n] = sum_k z[m,k] * w[n,k];  blockIdx.x<8 -> q_w -> g_q, else k_w -> g_k
__global__ void __launch_bounds__(256)
qk_gemm(const float* __restrict__ qw, const float* __restrict__ kw) {
    __shared__ float As[32][72];
    __shared__ float Bs[32][72];
    int bx = blockIdx.x, by = blockIdx.y;
    const float* wsrc = (bx < 8) ? qw : kw;
    float* outp = (bx < 8) ? g_q : g_k;
    int ncol0 = (bx & 7) * 64, bm = by * 64;
    int tid = threadIdx.x;
    int tm = tid >> 4, tn = tid & 15;
    float acc[4][4];
    #pragma unroll
    for (int i = 0; i < 4; i++)
        #pragma unroll
        for (int j = 0; j < 4; j++) acc[i][j] = 0.f;

    for (int k0 = 0; k0 < 512; k0 += 32) {
        #pragma unroll
        for (int it = 0; it < 2; it++) {
            int idx = tid + it * 256;
            int r = idx >> 3, c4 = (idx & 7) * 4;
            float4 v = *(const float4*)(g_z + (size_t)(bm + r) * 512 + k0 + c4);
            As[c4+0][r] = v.x; As[c4+1][r] = v.y; As[c4+2][r] = v.z; As[c4+3][r] = v.w;
            float4 u = *(const float4*)(wsrc + (size_t)(ncol0 + r) * 512 + k0 + c4);
            Bs[c4+0][r] = u.x; Bs[c4+1][r] = u.y; Bs[c4+2][r] = u.z; Bs[c4+3][r] = u.w;
        }
        __syncthreads();
        #pragma unroll
        for (int kk = 0; kk < 32; kk++) {
            float4 a = *(const float4*)&As[kk][tm * 4];
            float4 b = *(const float4*)&Bs[kk][tn * 4];
            float ar[4] = {a.x, a.y, a.z, a.w};
            float br[4] = {b.x, b.y, b.z, b.w};
            #pragma unroll
            for (int i = 0; i < 4; i++)
                #pragma unroll
                for (int j = 0; j < 4; j++) acc[i][j] = fmaf(ar[i], br[j], acc[i][j]);
        }
        __syncthreads();
    }
    #pragma unroll
    for (int e = 0; e < 4; e++) {
        float4 o; o.x = acc[e][0]; o.y = acc[e][1]; o.z = acc[e][2]; o.w = acc[e][3];
        *(float4*)(outp + (size_t)(bm + tm * 4 + e) * 512 + ncol0 + tn * 4) = o;
    }
}

// ---------------- scores: warp-per-row, REDUX top-k ----------------
__device__ __forceinline__ unsigned fenc(float v) {
    int b = __float_as_int(v);
    return (b >= 0) ? ((unsigned)b | 0x80000000u) : ~(unsigned)b;
}
__device__ __forceinline__ float wmax(float v) {
    #pragma unroll
    for (int o = 16; o; o >>= 1) v = fmaxf(v, __shfl_xor_sync(0xffffffffu, v, o));
    return v;
}
__device__ __forceinline__ float wsum(float v) {
    #pragma unroll
    for (int o = 16; o; o >>= 1) v += __shfl_xor_sync(0xffffffffu, v, o);
    return v;
}

__global__ void __launch_bounds__(256)
scores2(const float* __restrict__ adj) {
    __shared__ float ks[64][128];
    int ih = blockIdx.x, h = blockIdx.y, b = blockIdx.z;
    int tid = threadIdx.x, lane = tid & 31, w = tid >> 5;

    {   // stage k-slice transposed: ks[d][j]
        int j = tid >> 1, dh = (tid & 1) * 32;
        const float* kp = g_k + (size_t)(b * 128 + j) * 512 + h * 64 + dh;
        #pragma unroll
        for (int f = 0; f < 8; f++) {
            float4 v = *(const float4*)(kp + f * 4);
            ks[dh + f*4 + 0][j] = v.x; ks[dh + f*4 + 1][j] = v.y;
            ks[dh + f*4 + 2][j] = v.z; ks[dh + f*4 + 3][j] = v.w;
        }
    }
    __syncthreads();

    for (int r = 0; r < 8; r++) {
        int i = ih * 64 + w * 8 + r;
        float2 qr = *(const float2*)(g_q + (size_t)(b * 128 + i) * 512 + h * 64 + lane * 2);
        float a0 = 0.f, a1 = 0.f, a2 = 0.f, a3 = 0.f;
        #pragma unroll
        for (int d = 0; d < 64; d++) {
            float qd = __shfl_sync(0xffffffffu, (d & 1) ? qr.y : qr.x, d >> 1);
            float4 kv = *(const float4*)&ks[d][lane * 4];
            a0 = fmaf(qd, kv.x, a0); a1 = fmaf(qd, kv.y, a1);
            a2 = fmaf(qd, kv.z, a2); a3 = fmaf(qd, kv.w, a3);
        }
        float4 adjv = *(const float4*)(adj + (size_t)(b * 128 + i) * 128 + lane * 4);
        float s4[4];
        s4[0] = a0 * SCALE + logf(fmaxf(adjv.x, 1e-12f));
        s4[1] = a1 * SCALE + logf(fmaxf(adjv.y, 1e-12f));
        s4[2] = a2 * SCALE + logf(fmaxf(adjv.z, 1e-12f));
        s4[3] = a3 * SCALE + logf(fmaxf(adjv.w, 1e-12f));

        float m = wmax(fmaxf(fmaxf(s4[0], s4[1]), fmaxf(s4[2], s4[3])));
        float e4[4];
        #pragma unroll
        for (int q = 0; q < 4; q++) e4[q] = expf(s4[q] - m);
        float sum1 = wsum(e4[0] + e4[1] + e4[2] + e4[3]);

        size_t rb = ((size_t)(b * 8 + h) * 128 + i) * 128;
        float4 rv; rv.x = e4[0]/sum1; rv.y = e4[1]/sum1; rv.z = e4[2]/sum1; rv.w = e4[3]/sum1;
        *(float4*)(g_raw + rb + lane * 4) = rv;

        unsigned u4[4];
        #pragma unroll
        for (int q = 0; q < 4; q++) u4[q] = fenc(s4[q]);
        int myj = 0;
        for (int itk = 0; itk < TOPK; itk++) {
            unsigned ub = u4[0]; int jb = lane * 4;
            #pragma unroll
            for (int q = 1; q < 4; q++)
                if (u4[q] > ub) { ub = u4[q]; jb = lane * 4 + q; }
            unsigned gm = __reduce_max_sync(0xffffffffu, ub);
            unsigned jm = (ub == gm) ? (unsigned)jb : 0xFFFFu;
            unsigned js = __reduce_min_sync(0xffffffffu, jm);
            if (lane == itk) myj = (int)js;
            if ((js >> 2) == (unsigned)lane) u4[js & 3] = 0u;
        }
        float es = 0.f;
        #pragma unroll
        for (int q = 0; q < 4; q++) if (u4[q] == 0u) es += e4[q];
        float sum2 = wsum(es);
        float4 av;
        av.x = (u4[0] == 0u) ? e4[0]/sum2 : 0.f;
        av.y = (u4[1] == 0u) ? e4[1]/sum2 : 0.f;
        av.z = (u4[2] == 0u) ? e4[2]/sum2 : 0.f;
        av.w = (u4[3] == 0u) ? e4[3]/sum2 : 0.f;
        *(float4*)(g_attn + rb + lane * 4) = av;
        if (lane < TOPK)
            g_idx[((size_t)(b * 8 + h) * 128 + i) * TOPK + lane] = myj;
    }
}

// ---------------- bf16 tensor GEMM with cp.async 3-stage ----------------
__device__ __forceinline__ void cp16(void* smem, const void* g) {
    unsigned s = (unsigned)__cvta_generic_to_shared(smem);
    asm volatile("cp.async.cg.shared.global [%0], [%1], 16;" :: "r"(s), "l"(g));
}
__device__ __forceinline__ void ldsm4(unsigned& r0, unsigned& r1, unsigned& r2, unsigned& r3,
                                      unsigned addr) {
    asm volatile("ldmatrix.sync.aligned.m8n8.x4.shared.b16 {%0,%1,%2,%3}, [%4];"
                 : "=r"(r0), "=r"(r1), "=r"(r2), "=r"(r3) : "r"(addr));
}
__device__ __forceinline__ void mma16816(float* c, const unsigned* a, const unsigned* b) {
    asm volatile(
        "mma.sync.aligned.m16n8k16.row.col.f32.bf16.bf16.f32 "
        "{%0,%1,%2,%3}, {%4,%5,%6,%7}, {%8,%9}, {%0,%1,%2,%3};"
        : "+f"(c[0]), "+f"(c[1]), "+f"(c[2]), "+f"(c[3])
        : "r"(a[0]), "r"(a[1]), "r"(a[2]), "r"(a[3]), "r"(b[0]), "r"(b[1]));
}

#define STAGE_B 20480   // A tile 128*80B + B tile 128*80B

template <int MODE>
__global__ void __launch_bounds__(256)
mma_gemm3(const bf16* __restrict__ A, const bf16* __restrict__ W, void* __restrict__ Cv,
          const float* __restrict__ hval, const float* __restrict__ rs) {
    extern __shared__ __align__(16) char dynsm[];
    int tid = threadIdx.x;
    int lane = tid & 31, wid = tid >> 5;
    int wm = wid >> 2, wn = wid & 3;
    int brow = blockIdx.y * 128, bcol = blockIdx.x * 128;

    const bf16* asrc = (tid < 128) ? (A + (size_t)(brow + tid) * 512)
                                   : (W + (size_t)(bcol + tid - 128) * 512);
    char* sdst0 = dynsm + ((tid < 128) ? tid * 80 : (10240 + (tid - 128) * 80));

    unsigned smBase = (unsigned)__cvta_generic_to_shared(dynsm);
    unsigned aOff = (unsigned)((wm * 64 + (lane & 15)) * 80 + ((lane >> 4) << 4));
    unsigned bOff = (unsigned)(10240 + (wn * 32 + ((lane >> 3) & 1) * 8 + (lane & 7)) * 80
                               + ((lane >> 4) << 4));

    float acc[4][4][4];
    #pragma unroll
    for (int i = 0; i < 4; i++)
        #pragma unroll
        for (int j = 0; j < 4; j++)
            #pragma unroll
            for (int e = 0; e < 4; e++) acc[i][j][e] = 0.f;

    // prologue: stages 0,1
    #pragma unroll
    for (int s = 0; s < 2; s++) {
        char* dst = sdst0 + s * STAGE_B;
        const bf16* src = asrc + s * 32;
        #pragma unroll
        for (int c = 0; c < 4; c++) cp16(dst + c * 16, src + c * 8);
        asm volatile("cp.async.commit_group;");
    }

    #pragma unroll 1
    for (int it = 0; it < 16; it++) {
        if (it < 14) asm volatile("cp.async.wait_group 1;");
        else         asm volatile("cp.async.wait_group 0;");
        __syncthreads();
        if (it + 2 < 16) {
            int s = it + 2;
            char* dst = sdst0 + (s % 3) * STAGE_B;
            const bf16* src = asrc + s * 32;
            #pragma unroll
            for (int c = 0; c < 4; c++) cp16(dst + c * 16, src + c * 8);
            asm volatile("cp.async.commit_group;");
        }
        unsigned base = smBase + (unsigned)((it % 3) * STAGE_B);
        #pragma unroll
        for (int ks = 0; ks < 2; ks++) {
            unsigned a[4][4], b[4][2];
            #pragma unroll
            for (int mi = 0; mi < 4; mi++)
                ldsm4(a[mi][0], a[mi][1], a[mi][2], a[mi][3],
                      base + aOff + mi * (16 * 80) + ks * 32);
            #pragma unroll
            for (int pr = 0; pr < 2; pr++)
                ldsm4(b[2*pr][0], b[2*pr+1][0], b[2*pr][1], b[2*pr+1][1],
                      base + bOff + pr * (16 * 80) + ks * 32);
            #pragma unroll
            for (int mi = 0; mi < 4; mi++)
                #pragma unroll
                for (int ni = 0; ni < 4; ni++)
                    mma16816(acc[mi][ni], a[mi], b[ni]);
        }
    }

    #pragma unroll
    for (int mi = 0; mi < 4; mi++) {
        int r0 = brow + wm * 64 + mi * 16 + (lane >> 2);
        #pragma unroll
        for (int half = 0; half < 2; half++) {
            int r = r0 + half * 8;
            float sc = 1.f;
            if (MODE == 1) {
                int nseg = (r / Tt) % Nn;
                sc = fminf(fmaxf(rs[nseg], 0.f), 1.f);
            }
            #pragma unroll
            for (int ni = 0; ni < 4; ni++) {
                int c = bcol + wn * 32 + ni * 8 + (lane & 3) * 2;
                float x = acc[mi][ni][half * 2 + 0];
                float y = acc[mi][ni][half * 2 + 1];
                if (MODE == 0) {
                    *(__nv_bfloat162*)((bf16*)Cv + (size_t)r * 512 + c) =
                        __floats2bfloat162_rn(x, y);
                } else {
                    const float2 hv = *(const float2*)(hval + (size_t)r * 512 + c);
                    float2 o; o.x = hv.x + x * sc; o.y = hv.y + y * sc;
                    *(float2*)((float*)Cv + (size_t)r * 512 + c) = o;
                }
            }
        }
    }
}

// ---------------- mixed: smem-tiled sparse mix ----------------
__global__ void __launch_bounds__(256)
mixed2(const bf16* __restrict__ v, bf16* __restrict__ mixed) {
    __shared__ bf16 sv[128][128];
    __shared__ unsigned char su[128][16];
    __shared__ float swt[128][16];
    int nt = blockIdx.x, h = blockIdx.y, b = blockIdx.z;
    int tid = threadIdx.x, lane = tid & 31, w = tid >> 5;

    {   // stage v chunk [128 j][128 n], n = tt*64 + d
        int j = tid >> 1, tt = tid & 1;
        const uint4* src = (const uint4*)(v + ((size_t)(b * 128 + j) * 64 + nt * 2 + tt) * 512
                                            + h * 64);
        uint4* dst = (uint4*)&sv[j][tt * 64];
        #pragma unroll
        for (int c = 0; c < 8; c++) dst[c] = src[c];
    }
    {   // stage topk idx + weights (weights read from dense attn)
        int base = (b * 8 + h) * 128;
        #pragma unroll
        for (int e = tid * 8; e < tid * 8 + 8; e++) {
            int i = e >> 4, kk = e & 15;
            int j = g_idx[(size_t)(base + i) * 16 + kk];
            su[i][kk] = (unsigned char)j;
            swt[i][kk] = g_attn[(size_t)(base + i) * 128 + j];
        }
    }
    __syncthreads();

    int tt = lane >> 4, d = (lane & 15) * 4;
    for (int r = 0; r < 16; r++) {
        int i = w * 16 + r;
        float a0 = 0.f, a1 = 0.f, a2 = 0.f, a3 = 0.f;
        #pragma unroll
        for (int kk = 0; kk < 16; kk++) {
            int j = su[i][kk];
            float wt = swt[i][kk];
            uint2 vv = *(const uint2*)&sv[j][lane * 4];
            float2 f0 = __bfloat1622float2(*(__nv_bfloat162*)&vv.x);
            float2 f1 = __bfloat1622float2(*(__nv_bfloat162*)&vv.y);
            a0 = fmaf(wt, f0.x, a0); a1 = fmaf(wt, f0.y, a1);
            a2 = fmaf(wt, f1.x, a2); a3 = fmaf(wt, f1.y, a3);
        }
        __nv_bfloat162 o0 = __floats2bfloat162_rn(a0, a1);
        __nv_bfloat162 o1 = __floats2bfloat162_rn(a2, a3);
        uint2 ov; ov.x = *(unsigned*)&o0; ov.y = *(unsigned*)&o1;
        *(uint2*)(mixed + ((size_t)(b * 128 + i) * 64 + nt * 2 + tt) * 512 + h * 64 + d) = ov;
    }
}

// ---------------- head means ----------------
__global__ void means_kernel(float* __restrict__ out_attn, float* __restrict__ out_raw) {
    int idx = blockIdx.x * 256 + threadIdx.x;
    if (idx >= Bb * Nn * Nn) return;
    int b = idx / (Nn * Nn);
    int rem = idx % (Nn * Nn);
    float sa = 0.f, sr = 0.f;
    #pragma unroll
    for (int h = 0; h < Hh; h++) {
        size_t p = ((size_t)(b * Hh + h)) * Nn * Nn + rem;
        sa += g_attn[p];
        sr += g_raw[p];
    }
    out_attn[idx] = sa * (1.0f / Hh);
    out_raw[idx]  = sr * (1.0f / Hh);
}

// ---------------- launch ----------------
extern "C" void kernel_launch(void* const* d_in, const int* in_sizes, int n_in,
                              void* d_out, int out_size) {
    const float* h_val = (const float*)d_in[0];
    const float* h_map = (const float*)d_in[1];
    const float* adj   = (const float*)d_in[2];
    const float* q_w   = (const float*)d_in[3];
    const float* k_w   = (const float*)d_in[4];
    const float* v_w   = (const float*)d_in[5];
    const float* o_w   = (const float*)d_in[6];
    const float* rs    = (const float*)d_in[7];
    float* out = (float*)d_out;

    bf16 *hvb, *vwb, *owb, *v, *mixed;
    cudaGetSymbolAddress((void**)&hvb,   g_hvb);
    cudaGetSymbolAddress((void**)&vwb,   g_vwb);
    cudaGetSymbolAddress((void**)&owb,   g_owb);
    cudaGetSymbolAddress((void**)&v,     g_v);
    cudaGetSymbolAddress((void**)&mixed, g_mixed);

    cudaFuncSetAttribute(mma_gemm3<0>, cudaFuncAttributeMaxDynamicSharedMemorySize, 3 * STAGE_B);
    cudaFuncSetAttribute(mma_gemm3<1>, cudaFuncAttributeMaxDynamicSharedMemorySize, 3 * STAGE_B);

    f2bf<<<(OUT0_ELEMS/4 + 255)/256, 256>>>((const float4*)h_val, (uint2*)hvb, OUT0_ELEMS/4);
    f2bf<<<(Dd*Dd/4 + 255)/256, 256>>>((const float4*)v_w, (uint2*)vwb, Dd*Dd/4);
    f2bf<<<(Dd*Dd/4 + 255)/256, 256>>>((const float4*)o_w, (uint2*)owb, Dd*Dd/4);

    zmap_kernel<<<Bb * Nn, Dd>>>(h_map);
    qk_gemm<<<dim3(16, 16), 256>>>(q_w, k_w);
    scores2<<<dim3(2, Hh, Bb), 256>>>(adj);

    mma_gemm3<0><<<dim3(4, 512), 256, 3 * STAGE_B>>>(hvb, vwb, (void*)v, nullptr, nullptr);
    mixed2<<<dim3(32, Hh, Bb), 256>>>(v, mixed);
    mma_gemm3<1><<<dim3(4, 512), 256, 3 * STAGE_B>>>(mixed, owb, (void*)out, h_val, rs);

    means_kernel<<<(MEAN_ELEMS + 255)/256, 256>>>(out + OUT0_ELEMS, out + OUT0_ELEMS + MEAN_ELEMS);
}

// round 6
// speedup vs baseline: 3.4796x; 1.0064x over previous
#include <cuda_runtime.h>
#include <cuda_bf16.h>
#include <math.h>
#include <stdint.h>

#define Bb 8
#define Nn 128
#define Tt 64
#define Dd 512
#define Hh 8
#define HD 64
#define TOPK 16
#define SCALE 0.125f

#define OUT0_ELEMS (Bb*Nn*Tt*Dd)
#define MEAN_ELEMS (Bb*Nn*Nn)

typedef __nv_bfloat16 bf16;

// ---------------- static device scratch ----------------
__device__ float g_z[Bb*Nn*Dd];
__device__ float g_q[Bb*Nn*Dd];
__device__ float g_k[Bb*Nn*Dd];
__device__ float g_attn[Bb*Hh*Nn*Nn];
__device__ float g_raw[Bb*Hh*Nn*Nn];
__device__ int   g_idx[Bb*Hh*Nn*TOPK];
__device__ bf16  g_hvb[Bb*Nn*Tt*Dd];
__device__ bf16  g_vwb[Dd*Dd];
__device__ bf16  g_owb[Dd*Dd];
__device__ bf16  g_v[Bb*Nn*Tt*Dd];
__device__ bf16  g_mixed[Bb*Nn*Tt*Dd];

// ---------------- fp32 -> bf16 ----------------
__global__ void f2bf(const float4* __restrict__ x, uint2* __restrict__ y, int n4) {
    int i = blockIdx.x * 256 + threadIdx.x;
    if (i >= n4) return;
    float4 f = x[i];
    __nv_bfloat162 a = __floats2bfloat162_rn(f.x, f.y);
    __nv_bfloat162 b = __floats2bfloat162_rn(f.z, f.w);
    uint2 u; u.x = *(unsigned*)&a; u.y = *(unsigned*)&b;
    y[i] = u;
}

// ---------------- z_map mean ----------------
__global__ void zmap_kernel(const float* __restrict__ hmap) {
    int bn = blockIdx.x;
    int d  = threadIdx.x;
    const float* p = hmap + (size_t)bn * Tt * Dd + d;
    float s = 0.f;
    #pragma unroll 8
    for (int t = 0; t < Tt; t++) s += p[t * Dd];
    g_z[bn * Dd + d] = s * (1.0f / Tt);
}

// ---------------- q/k projection ----------------
__global__ void __launch_bounds__(256)
qk_gemm(const float* __restrict__ qw, const float* __restrict__ kw) {
    __shared__ float As[32][72];
    __shared__ float Bs[32][72];
    int bx = blockIdx.x, by = blockIdx.y;
    const float* wsrc = (bx < 8) ? qw : kw;
    float* outp = (bx < 8) ? g_q : g_k;
    int ncol0 = (bx & 7) * 64, bm = by * 64;
    int tid = threadIdx.x;
    int tm = tid >> 4, tn = tid & 15;
    float acc[4][4];
    #pragma unroll
    for (int i = 0; i < 4; i++)
        #pragma unroll
        for (int j = 0; j < 4; j++) acc[i][j] = 0.f;

    for (int k0 = 0; k0 < 512; k0 += 32) {
        #pragma unroll
        for (int it = 0; it < 2; it++) {
            int idx = tid + it * 256;
            int r = idx >> 3, c4 = (idx & 7) * 4;
            float4 v = *(const float4*)(g_z + (size_t)(bm + r) * 512 + k0 + c4);
            As[c4+0][r] = v.x; As[c4+1][r] = v.y; As[c4+2][r] = v.z; As[c4+3][r] = v.w;
            float4 u = *(const float4*)(wsrc + (size_t)(ncol0 + r) * 512 + k0 + c4);
            Bs[c4+0][r] = u.x; Bs[c4+1][r] = u.y; Bs[c4+2][r] = u.z; Bs[c4+3][r] = u.w;
        }
        __syncthreads();
        #pragma unroll
        for (int kk = 0; kk < 32; kk++) {
            float4 a = *(const float4*)&As[kk][tm * 4];
            float4 b = *(const float4*)&Bs[kk][tn * 4];
            float ar[4] = {a.x, a.y, a.z, a.w};
            float br[4] = {b.x, b.y, b.z, b.w};
            #pragma unroll
            for (int i = 0; i < 4; i++)
                #pragma unroll
                for (int j = 0; j < 4; j++) acc[i][j] = fmaf(ar[i], br[j], acc[i][j]);
        }
        __syncthreads();
    }
    #pragma unroll
    for (int e = 0; e < 4; e++) {
        float4 o; o.x = acc[e][0]; o.y = acc[e][1]; o.z = acc[e][2]; o.w = acc[e][3];
        *(float4*)(outp + (size_t)(bm + tm * 4 + e) * 512 + ncol0 + tn * 4) = o;
    }
}

// ---------------- scores (warp-per-row, REDUX topk) ----------------
__device__ __forceinline__ unsigned fenc(float v) {
    int b = __float_as_int(v);
    return (b >= 0) ? ((unsigned)b | 0x80000000u) : ~(unsigned)b;
}
__device__ __forceinline__ float wmax(float v) {
    #pragma unroll
    for (int o = 16; o; o >>= 1) v = fmaxf(v, __shfl_xor_sync(0xffffffffu, v, o));
    return v;
}
__device__ __forceinline__ float wsum(float v) {
    #pragma unroll
    for (int o = 16; o; o >>= 1) v += __shfl_xor_sync(0xffffffffu, v, o);
    return v;
}

__global__ void __launch_bounds__(256)
scores2(const float* __restrict__ adj) {
    __shared__ float ks[64][128];
    int ih = blockIdx.x, h = blockIdx.y, b = blockIdx.z;
    int tid = threadIdx.x, lane = tid & 31, w = tid >> 5;

    {
        int j = tid >> 1, dh = (tid & 1) * 32;
        const float* kp = g_k + (size_t)(b * 128 + j) * 512 + h * 64 + dh;
        #pragma unroll
        for (int f = 0; f < 8; f++) {
            float4 v = *(const float4*)(kp + f * 4);
            ks[dh + f*4 + 0][j] = v.x; ks[dh + f*4 + 1][j] = v.y;
            ks[dh + f*4 + 2][j] = v.z; ks[dh + f*4 + 3][j] = v.w;
        }
    }
    __syncthreads();

    for (int r = 0; r < 8; r++) {
        int i = ih * 64 + w * 8 + r;
        float2 qr = *(const float2*)(g_q + (size_t)(b * 128 + i) * 512 + h * 64 + lane * 2);
        float a0 = 0.f, a1 = 0.f, a2 = 0.f, a3 = 0.f;
        #pragma unroll
        for (int d = 0; d < 64; d++) {
            float qd = __shfl_sync(0xffffffffu, (d & 1) ? qr.y : qr.x, d >> 1);
            float4 kv = *(const float4*)&ks[d][lane * 4];
            a0 = fmaf(qd, kv.x, a0); a1 = fmaf(qd, kv.y, a1);
            a2 = fmaf(qd, kv.z, a2); a3 = fmaf(qd, kv.w, a3);
        }
        float4 adjv = *(const float4*)(adj + (size_t)(b * 128 + i) * 128 + lane * 4);
        float s4[4];
        s4[0] = a0 * SCALE + logf(fmaxf(adjv.x, 1e-12f));
        s4[1] = a1 * SCALE + logf(fmaxf(adjv.y, 1e-12f));
        s4[2] = a2 * SCALE + logf(fmaxf(adjv.z, 1e-12f));
        s4[3] = a3 * SCALE + logf(fmaxf(adjv.w, 1e-12f));

        float m = wmax(fmaxf(fmaxf(s4[0], s4[1]), fmaxf(s4[2], s4[3])));
        float e4[4];
        #pragma unroll
        for (int q = 0; q < 4; q++) e4[q] = expf(s4[q] - m);
        float sum1 = wsum(e4[0] + e4[1] + e4[2] + e4[3]);

        size_t rb = ((size_t)(b * 8 + h) * 128 + i) * 128;
        float4 rv; rv.x = e4[0]/sum1; rv.y = e4[1]/sum1; rv.z = e4[2]/sum1; rv.w = e4[3]/sum1;
        *(float4*)(g_raw + rb + lane * 4) = rv;

        unsigned u4[4];
        #pragma unroll
        for (int q = 0; q < 4; q++) u4[q] = fenc(s4[q]);
        int myj = 0;
        for (int itk = 0; itk < TOPK; itk++) {
            unsigned ub = u4[0]; int jb = lane * 4;
            #pragma unroll
            for (int q = 1; q < 4; q++)
                if (u4[q] > ub) { ub = u4[q]; jb = lane * 4 + q; }
            unsigned gm = __reduce_max_sync(0xffffffffu, ub);
            unsigned jm = (ub == gm) ? (unsigned)jb : 0xFFFFu;
            unsigned js = __reduce_min_sync(0xffffffffu, jm);
            if (lane == itk) myj = (int)js;
            if ((js >> 2) == (unsigned)lane) u4[js & 3] = 0u;
        }
        float es = 0.f;
        #pragma unroll
        for (int q = 0; q < 4; q++) if (u4[q] == 0u) es += e4[q];
        float sum2 = wsum(es);
        float4 av;
        av.x = (u4[0] == 0u) ? e4[0]/sum2 : 0.f;
        av.y = (u4[1] == 0u) ? e4[1]/sum2 : 0.f;
        av.z = (u4[2] == 0u) ? e4[2]/sum2 : 0.f;
        av.w = (u4[3] == 0u) ? e4[3]/sum2 : 0.f;
        *(float4*)(g_attn + rb + lane * 4) = av;
        if (lane < TOPK)
            g_idx[((size_t)(b * 8 + h) * 128 + i) * TOPK + lane] = myj;
    }
}

// ================== bf16 HMMA GEMM: C = A[M,512] * W[512,512]^T ==================
// 128x128 CTA tile, 128 threads (2x2 warps of 64x64), BK=32, 4-stage cp.async.
__device__ __forceinline__ void cp16(void* smem, const void* g) {
    unsigned s = (unsigned)__cvta_generic_to_shared(smem);
    asm volatile("cp.async.cg.shared.global [%0], [%1], 16;" :: "r"(s), "l"(g));
}
__device__ __forceinline__ void ldsm4(unsigned& r0, unsigned& r1, unsigned& r2, unsigned& r3,
                                      unsigned addr) {
    asm volatile("ldmatrix.sync.aligned.m8n8.x4.shared.b16 {%0,%1,%2,%3}, [%4];"
                 : "=r"(r0), "=r"(r1), "=r"(r2), "=r"(r3) : "r"(addr));
}
__device__ __forceinline__ void mma16816(float* c, const unsigned* a, const unsigned* b) {
    asm volatile(
        "mma.sync.aligned.m16n8k16.row.col.f32.bf16.bf16.f32 "
        "{%0,%1,%2,%3}, {%4,%5,%6,%7}, {%8,%9}, {%0,%1,%2,%3};"
        : "+f"(c[0]), "+f"(c[1]), "+f"(c[2]), "+f"(c[3])
        : "r"(a[0]), "r"(a[1]), "r"(a[2]), "r"(a[3]), "r"(b[0]), "r"(b[1]));
}

#define STAGE_B 20480   // A tile 128 rows x 80B + B tile 128 rows x 80B
#define NSTG    4
#define GSMEM   (NSTG * STAGE_B)

template <int MODE>
__global__ void __launch_bounds__(128, 2)
mma_gemm4(const bf16* __restrict__ A, const bf16* __restrict__ W, void* __restrict__ Cv,
          const float* __restrict__ hval, const float* __restrict__ rs) {
    extern __shared__ __align__(16) char dynsm[];
    int tid = threadIdx.x;
    int lane = tid & 31, wid = tid >> 5;
    int wm = wid >> 1, wn = wid & 1;               // 2x2 warps, 64x64 each
    int brow = blockIdx.y * 128, bcol = blockIdx.x * 128;

    // staging: thread t -> A row t (4x16B) + B row t (4x16B)
    const bf16* aptr = A + (size_t)(brow + tid) * 512;
    const bf16* bptr = W + (size_t)(bcol + tid) * 512;
    char* aDst = dynsm + tid * 80;
    char* bDst = dynsm + 10240 + tid * 80;

    unsigned smBase = (unsigned)__cvta_generic_to_shared(dynsm);
    unsigned aOff = (unsigned)((wm * 64 + (lane & 15)) * 80 + ((lane >> 4) << 4));
    unsigned bOff = (unsigned)(10240 + (wn * 64 + ((lane >> 3) & 1) * 8 + (lane & 7)) * 80
                               + ((lane >> 4) << 4));

    float acc[4][8][4];
    #pragma unroll
    for (int i = 0; i < 4; i++)
        #pragma unroll
        for (int j = 0; j < 8; j++)
            #pragma unroll
            for (int e = 0; e < 4; e++) acc[i][j][e] = 0.f;

    // prologue: stages 0..2
    #pragma unroll
    for (int s = 0; s < 3; s++) {
        char* ad = aDst + s * STAGE_B;
        char* bd = bDst + s * STAGE_B;
        const bf16* as = aptr + s * 32;
        const bf16* bs = bptr + s * 32;
        #pragma unroll
        for (int c = 0; c < 4; c++) { cp16(ad + c * 16, as + c * 8); cp16(bd + c * 16, bs + c * 8); }
        asm volatile("cp.async.commit_group;");
    }

    #pragma unroll 1
    for (int it = 0; it < 16; it++) {
        if (it < 14)      asm volatile("cp.async.wait_group 2;");
        else if (it == 14) asm volatile("cp.async.wait_group 1;");
        else               asm volatile("cp.async.wait_group 0;");
        __syncthreads();
        if (it + 3 < 16) {
            int s = it + 3;
            char* ad = aDst + (s & 3) * STAGE_B;
            char* bd = bDst + (s & 3) * STAGE_B;
            const bf16* as = aptr + s * 32;
            const bf16* bs = bptr + s * 32;
            #pragma unroll
            for (int c = 0; c < 4; c++) { cp16(ad + c * 16, as + c * 8); cp16(bd + c * 16, bs + c * 8); }
            asm volatile("cp.async.commit_group;");
        }
        unsigned base = smBase + (unsigned)((it & 3) * STAGE_B);
        #pragma unroll
        for (int ks = 0; ks < 2; ks++) {
            unsigned a[4][4], b[8][2];
            #pragma unroll
            for (int mi = 0; mi < 4; mi++)
                ldsm4(a[mi][0], a[mi][1], a[mi][2], a[mi][3],
                      base + aOff + mi * (16 * 80) + ks * 32);
            #pragma unroll
            for (int pr = 0; pr < 4; pr++)
                ldsm4(b[2*pr][0], b[2*pr+1][0], b[2*pr][1], b[2*pr+1][1],
                      base + bOff + pr * (16 * 80) + ks * 32);
            #pragma unroll
            for (int mi = 0; mi < 4; mi++)
                #pragma unroll
                for (int ni = 0; ni < 8; ni++)
                    mma16816(acc[mi][ni], a[mi], b[ni]);
        }
    }

    // epilogue
    #pragma unroll
    for (int mi = 0; mi < 4; mi++) {
        int r0 = brow + wm * 64 + mi * 16 + (lane >> 2);
        #pragma unroll
        for (int half = 0; half < 2; half++) {
            int r = r0 + half * 8;
            float sc = 1.f;
            if (MODE == 1) {
                int nseg = (r / Tt) % Nn;
                sc = fminf(fmaxf(rs[nseg], 0.f), 1.f);
            }
            #pragma unroll
            for (int ni = 0; ni < 8; ni++) {
                int c = bcol + wn * 64 + ni * 8 + (lane & 3) * 2;
                float x = acc[mi][ni][half * 2 + 0];
                float y = acc[mi][ni][half * 2 + 1];
                if (MODE == 0) {
                    *(__nv_bfloat162*)((bf16*)Cv + (size_t)r * 512 + c) =
                        __floats2bfloat162_rn(x, y);
                } else {
                    const float2 hv = *(const float2*)(hval + (size_t)r * 512 + c);
                    float2 o; o.x = hv.x + x * sc; o.y = hv.y + y * sc;
                    *(float2*)((float*)Cv + (size_t)r * 512 + c) = o;
                }
            }
        }
    }
}

// ---------------- mixed: smem-tiled sparse mix ----------------
__global__ void __launch_bounds__(256)
mixed2(const bf16* __restrict__ v, bf16* __restrict__ mixed) {
    __shared__ bf16 sv[128][128];
    __shared__ unsigned char su[128][16];
    __shared__ float swt[128][16];
    int nt = blockIdx.x, h = blockIdx.y, b = blockIdx.z;
    int tid = threadIdx.x, lane = tid & 31, w = tid >> 5;

    {
        int j = tid >> 1, tt = tid & 1;
        const uint4* src = (const uint4*)(v + ((size_t)(b * 128 + j) * 64 + nt * 2 + tt) * 512
                                            + h * 64);
        uint4* dst = (uint4*)&sv[j][tt * 64];
        #pragma unroll
        for (int c = 0; c < 8; c++) dst[c] = src[c];
    }
    {
        int base = (b * 8 + h) * 128;
        #pragma unroll
        for (int e = tid * 8; e < tid * 8 + 8; e++) {
            int i = e >> 4, kk = e & 15;
            int j = g_idx[(size_t)(base + i) * 16 + kk];
            su[i][kk] = (unsigned char)j;
            swt[i][kk] = g_attn[(size_t)(base + i) * 128 + j];
        }
    }
    __syncthreads();

    int tt = lane >> 4;
    for (int r = 0; r < 16; r++) {
        int i = w * 16 + r;
        float a0 = 0.f, a1 = 0.f, a2 = 0.f, a3 = 0.f;
        #pragma unroll
        for (int kk = 0; kk < 16; kk++) {
            int j = su[i][kk];
            float wt = swt[i][kk];
            uint2 vv = *(const uint2*)&sv[j][lane * 4];
            float2 f0 = __bfloat1622float2(*(__nv_bfloat162*)&vv.x);
            float2 f1 = __bfloat1622float2(*(__nv_bfloat162*)&vv.y);
            a0 = fmaf(wt, f0.x, a0); a1 = fmaf(wt, f0.y, a1);
            a2 = fmaf(wt, f1.x, a2); a3 = fmaf(wt, f1.y, a3);
        }
        int d = (lane & 15) * 4;
        __nv_bfloat162 o0 = __floats2bfloat162_rn(a0, a1);
        __nv_bfloat162 o1 = __floats2bfloat162_rn(a2, a3);
        uint2 ov; ov.x = *(unsigned*)&o0; ov.y = *(unsigned*)&o1;
        *(uint2*)(mixed + ((size_t)(b * 128 + i) * 64 + nt * 2 + tt) * 512 + h * 64 + d) = ov;
    }
}

// ---------------- head means ----------------
__global__ void means_kernel(float* __restrict__ out_attn, float* __restrict__ out_raw) {
    int idx = blockIdx.x * 256 + threadIdx.x;
    if (idx >= Bb * Nn * Nn) return;
    int b = idx / (Nn * Nn);
    int rem = idx % (Nn * Nn);
    float sa = 0.f, sr = 0.f;
    #pragma unroll
    for (int h = 0; h < Hh; h++) {
        size_t p = ((size_t)(b * Hh + h)) * Nn * Nn + rem;
        sa += g_attn[p];
        sr += g_raw[p];
    }
    out_attn[idx] = sa * (1.0f / Hh);
    out_raw[idx]  = sr * (1.0f / Hh);
}

// ---------------- launch ----------------
extern "C" void kernel_launch(void* const* d_in, const int* in_sizes, int n_in,
                              void* d_out, int out_size) {
    const float* h_val = (const float*)d_in[0];
    const float* h_map = (const float*)d_in[1];
    const float* adj   = (const float*)d_in[2];
    const float* q_w   = (const float*)d_in[3];
    const float* k_w   = (const float*)d_in[4];
    const float* v_w   = (const float*)d_in[5];
    const float* o_w   = (const float*)d_in[6];
    const float* rs    = (const float*)d_in[7];
    float* out = (float*)d_out;

    bf16 *hvb, *vwb, *owb, *v, *mixed;
    cudaGetSymbolAddress((void**)&hvb,   g_hvb);
    cudaGetSymbolAddress((void**)&vwb,   g_vwb);
    cudaGetSymbolAddress((void**)&owb,   g_owb);
    cudaGetSymbolAddress((void**)&v,     g_v);
    cudaGetSymbolAddress((void**)&mixed, g_mixed);

    cudaFuncSetAttribute(mma_gemm4<0>, cudaFuncAttributeMaxDynamicSharedMemorySize, GSMEM);
    cudaFuncSetAttribute(mma_gemm4<1>, cudaFuncAttributeMaxDynamicSharedMemorySize, GSMEM);

    f2bf<<<(OUT0_ELEMS/4 + 255)/256, 256>>>((const float4*)h_val, (uint2*)hvb, OUT0_ELEMS/4);
    f2bf<<<(Dd*Dd/4 + 255)/256, 256>>>((const float4*)v_w, (uint2*)vwb, Dd*Dd/4);
    f2bf<<<(Dd*Dd/4 + 255)/256, 256>>>((const float4*)o_w, (uint2*)owb, Dd*Dd/4);

    zmap_kernel<<<Bb * Nn, Dd>>>(h_map);
    qk_gemm<<<dim3(16, 16), 256>>>(q_w, k_w);
    scores2<<<dim3(2, Hh, Bb), 256>>>(adj);

    mma_gemm4<0><<<dim3(4, 512), 128, GSMEM>>>(hvb, vwb, (void*)v, nullptr, nullptr);
    mixed2<<<dim3(32, Hh, Bb), 256>>>(v, mixed);
    mma_gemm4<1><<<dim3(4, 512), 128, GSMEM>>>(mixed, owb, (void*)out, h_val, rs);

    means_kernel<<<(MEAN_ELEMS + 255)/256, 256>>>(out + OUT0_ELEMS, out + OUT0_ELEMS + MEAN_ELEMS);
}

// round 8
// speedup vs baseline: 3.5480x; 1.0196x over previous
#include <cuda_runtime.h>
#include <cuda_bf16.h>
#include <math.h>
#include <stdint.h>

#define Bb 8
#define Nn 128
#define Tt 64
#define Dd 512
#define Hh 8
#define HD 64
#define TOPK 16
#define SCALE 0.125f

#define OUT0_ELEMS (Bb*Nn*Tt*Dd)
#define MEAN_ELEMS (Bb*Nn*Nn)

typedef __nv_bfloat16 bf16;

// ---------------- static device scratch ----------------
__device__ float g_z[Bb*Nn*Dd];
__device__ float g_q[Bb*Nn*Dd];
__device__ float g_k[Bb*Nn*Dd];
__device__ float g_attn[Bb*Hh*Nn*Nn];
__device__ float g_raw[Bb*Hh*Nn*Nn];
__device__ int   g_idx[Bb*Hh*Nn*TOPK];
__device__ bf16  g_hvb[Bb*Nn*Tt*Dd];
__device__ bf16  g_vwb[Dd*Dd];
__device__ bf16  g_owb[Dd*Dd];
__device__ bf16  g_v[Bb*Nn*Tt*Dd];
__device__ bf16  g_mixed[Bb*Nn*Tt*Dd];

// ---------------- fp32 -> bf16 ----------------
__global__ void f2bf(const float4* __restrict__ x, uint2* __restrict__ y, int n4) {
    int i = blockIdx.x * 256 + threadIdx.x;
    if (i >= n4) return;
    float4 f = x[i];
    __nv_bfloat162 a = __floats2bfloat162_rn(f.x, f.y);
    __nv_bfloat162 b = __floats2bfloat162_rn(f.z, f.w);
    uint2 u; u.x = *(unsigned*)&a; u.y = *(unsigned*)&b;
    y[i] = u;
}

// ---------------- z_map mean ----------------
__global__ void zmap_kernel(const float* __restrict__ hmap) {
    int bn = blockIdx.x;
    int d  = threadIdx.x;
    const float* p = hmap + (size_t)bn * Tt * Dd + d;
    float s = 0.f;
    #pragma unroll 8
    for (int t = 0; t < Tt; t++) s += p[t * Dd];
    g_z[bn * Dd + d] = s * (1.0f / Tt);
}

// ---------------- q/k projection ----------------
__global__ void __launch_bounds__(256)
qk_gemm(const float* __restrict__ qw, const float* __restrict__ kw) {
    __shared__ float As[32][72];
    __shared__ float Bs[32][72];
    int bx = blockIdx.x, by = blockIdx.y;
    const float* wsrc = (bx < 8) ? qw : kw;
    float* outp = (bx < 8) ? g_q : g_k;
    int ncol0 = (bx & 7) * 64, bm = by * 64;
    int tid = threadIdx.x;
    int tm = tid >> 4, tn = tid & 15;
    float acc[4][4];
    #pragma unroll
    for (int i = 0; i < 4; i++)
        #pragma unroll
        for (int j = 0; j < 4; j++) acc[i][j] = 0.f;

    for (int k0 = 0; k0 < 512; k0 += 32) {
        #pragma unroll
        for (int it = 0; it < 2; it++) {
            int idx = tid + it * 256;
            int r = idx >> 3, c4 = (idx & 7) * 4;
            float4 v = *(const float4*)(g_z + (size_t)(bm + r) * 512 + k0 + c4);
            As[c4+0][r] = v.x; As[c4+1][r] = v.y; As[c4+2][r] = v.z; As[c4+3][r] = v.w;
            float4 u = *(const float4*)(wsrc + (size_t)(ncol0 + r) * 512 + k0 + c4);
            Bs[c4+0][r] = u.x; Bs[c4+1][r] = u.y; Bs[c4+2][r] = u.z; Bs[c4+3][r] = u.w;
        }
        __syncthreads();
        #pragma unroll
        for (int kk = 0; kk < 32; kk++) {
            float4 a = *(const float4*)&As[kk][tm * 4];
            float4 b = *(const float4*)&Bs[kk][tn * 4];
            float ar[4] = {a.x, a.y, a.z, a.w};
            float br[4] = {b.x, b.y, b.z, b.w};
            #pragma unroll
            for (int i = 0; i < 4; i++)
                #pragma unroll
                for (int j = 0; j < 4; j++) acc[i][j] = fmaf(ar[i], br[j], acc[i][j]);
        }
        __syncthreads();
    }
    #pragma unroll
    for (int e = 0; e < 4; e++) {
        float4 o; o.x = acc[e][0]; o.y = acc[e][1]; o.z = acc[e][2]; o.w = acc[e][3];
        *(float4*)(outp + (size_t)(bm + tm * 4 + e) * 512 + ncol0 + tn * 4) = o;
    }
}

// ---------------- scores (warp-per-row, REDUX topk) ----------------
__device__ __forceinline__ unsigned fenc(float v) {
    int b = __float_as_int(v);
    return (b >= 0) ? ((unsigned)b | 0x80000000u) : ~(unsigned)b;
}
__device__ __forceinline__ float wmax(float v) {
    #pragma unroll
    for (int o = 16; o; o >>= 1) v = fmaxf(v, __shfl_xor_sync(0xffffffffu, v, o));
    return v;
}
__device__ __forceinline__ float wsum(float v) {
    #pragma unroll
    for (int o = 16; o; o >>= 1) v += __shfl_xor_sync(0xffffffffu, v, o);
    return v;
}

__global__ void __launch_bounds__(256)
scores2(const float* __restrict__ adj) {
    __shared__ float ks[64][128];
    int ih = blockIdx.x, h = blockIdx.y, b = blockIdx.z;
    int tid = threadIdx.x, lane = tid & 31, w = tid >> 5;

    {
        int j = tid >> 1, dh = (tid & 1) * 32;
        const float* kp = g_k + (size_t)(b * 128 + j) * 512 + h * 64 + dh;
        #pragma unroll
        for (int f = 0; f < 8; f++) {
            float4 v = *(const float4*)(kp + f * 4);
            ks[dh + f*4 + 0][j] = v.x; ks[dh + f*4 + 1][j] = v.y;
            ks[dh + f*4 + 2][j] = v.z; ks[dh + f*4 + 3][j] = v.w;
        }
    }
    __syncthreads();

    for (int r = 0; r < 8; r++) {
        int i = ih * 64 + w * 8 + r;
        float2 qr = *(const float2*)(g_q + (size_t)(b * 128 + i) * 512 + h * 64 + lane * 2);
        float a0 = 0.f, a1 = 0.f, a2 = 0.f, a3 = 0.f;
        #pragma unroll
        for (int d = 0; d < 64; d++) {
            float qd = __shfl_sync(0xffffffffu, (d & 1) ? qr.y : qr.x, d >> 1);
            float4 kv = *(const float4*)&ks[d][lane * 4];
            a0 = fmaf(qd, kv.x, a0); a1 = fmaf(qd, kv.y, a1);
            a2 = fmaf(qd, kv.z, a2); a3 = fmaf(qd, kv.w, a3);
        }
        float4 adjv = *(const float4*)(adj + (size_t)(b * 128 + i) * 128 + lane * 4);
        float s4[4];
        s4[0] = a0 * SCALE + logf(fmaxf(adjv.x, 1e-12f));
        s4[1] = a1 * SCALE + logf(fmaxf(adjv.y, 1e-12f));
        s4[2] = a2 * SCALE + logf(fmaxf(adjv.z, 1e-12f));
        s4[3] = a3 * SCALE + logf(fmaxf(adjv.w, 1e-12f));

        float m = wmax(fmaxf(fmaxf(s4[0], s4[1]), fmaxf(s4[2], s4[3])));
        float e4[4];
        #pragma unroll
        for (int q = 0; q < 4; q++) e4[q] = expf(s4[q] - m);
        float sum1 = wsum(e4[0] + e4[1] + e4[2] + e4[3]);

        size_t rb = ((size_t)(b * 8 + h) * 128 + i) * 128;
        float4 rv; rv.x = e4[0]/sum1; rv.y = e4[1]/sum1; rv.z = e4[2]/sum1; rv.w = e4[3]/sum1;
        *(float4*)(g_raw + rb + lane * 4) = rv;

        unsigned u4[4];
        #pragma unroll
        for (int q = 0; q < 4; q++) u4[q] = fenc(s4[q]);
        int myj = 0;
        for (int itk = 0; itk < TOPK; itk++) {
            unsigned ub = u4[0]; int jb = lane * 4;
            #pragma unroll
            for (int q = 1; q < 4; q++)
                if (u4[q] > ub) { ub = u4[q]; jb = lane * 4 + q; }
            unsigned gm = __reduce_max_sync(0xffffffffu, ub);
            unsigned jm = (ub == gm) ? (unsigned)jb : 0xFFFFu;
            unsigned js = __reduce_min_sync(0xffffffffu, jm);
            if (lane == itk) myj = (int)js;
            if ((js >> 2) == (unsigned)lane) u4[js & 3] = 0u;
        }
        float es = 0.f;
        #pragma unroll
        for (int q = 0; q < 4; q++) if (u4[q] == 0u) es += e4[q];
        float sum2 = wsum(es);
        float4 av;
        av.x = (u4[0] == 0u) ? e4[0]/sum2 : 0.f;
        av.y = (u4[1] == 0u) ? e4[1]/sum2 : 0.f;
        av.z = (u4[2] == 0u) ? e4[2]/sum2 : 0.f;
        av.w = (u4[3] == 0u) ? e4[3]/sum2 : 0.f;
        *(float4*)(g_attn + rb + lane * 4) = av;
        if (lane < TOPK)
            g_idx[((size_t)(b * 8 + h) * 128 + i) * TOPK + lane] = myj;
    }
}

// ================== bf16 HMMA GEMM (R6 proven) ==================
__device__ __forceinline__ void cp16(void* smem, const void* g) {
    unsigned s = (unsigned)__cvta_generic_to_shared(smem);
    asm volatile("cp.async.cg.shared.global [%0], [%1], 16;" :: "r"(s), "l"(g));
}
__device__ __forceinline__ void ldsm4(unsigned& r0, unsigned& r1, unsigned& r2, unsigned& r3,
                                      unsigned addr) {
    asm volatile("ldmatrix.sync.aligned.m8n8.x4.shared.b16 {%0,%1,%2,%3}, [%4];"
                 : "=r"(r0), "=r"(r1), "=r"(r2), "=r"(r3) : "r"(addr));
}
__device__ __forceinline__ void mma16816(float* c, const unsigned* a, const unsigned* b) {
    asm volatile(
        "mma.sync.aligned.m16n8k16.row.col.f32.bf16.bf16.f32 "
        "{%0,%1,%2,%3}, {%4,%5,%6,%7}, {%8,%9}, {%0,%1,%2,%3};"
        : "+f"(c[0]), "+f"(c[1]), "+f"(c[2]), "+f"(c[3])
        : "r"(a[0]), "r"(a[1]), "r"(a[2]), "r"(a[3]), "r"(b[0]), "r"(b[1]));
}

#define STAGE_B 20480
#define NSTG    4
#define GSMEM   (NSTG * STAGE_B)

template <int MODE>
__global__ void __launch_bounds__(128, 2)
mma_gemm4(const bf16* __restrict__ A, const bf16* __restrict__ W, void* __restrict__ Cv,
          const float* __restrict__ hval, const float* __restrict__ rs) {
    extern __shared__ __align__(16) char dynsm[];
    int tid = threadIdx.x;
    int lane = tid & 31, wid = tid >> 5;
    int wm = wid >> 1, wn = wid & 1;
    int brow = blockIdx.y * 128, bcol = blockIdx.x * 128;

    const bf16* aptr = A + (size_t)(brow + tid) * 512;
    const bf16* bptr = W + (size_t)(bcol + tid) * 512;
    char* aDst = dynsm + tid * 80;
    char* bDst = dynsm + 10240 + tid * 80;

    unsigned smBase = (unsigned)__cvta_generic_to_shared(dynsm);
    unsigned aOff = (unsigned)((wm * 64 + (lane & 15)) * 80 + ((lane >> 4) << 4));
    unsigned bOff = (unsigned)(10240 + (wn * 64 + ((lane >> 3) & 1) * 8 + (lane & 7)) * 80
                               + ((lane >> 4) << 4));

    float acc[4][8][4];
    #pragma unroll
    for (int i = 0; i < 4; i++)
        #pragma unroll
        for (int j = 0; j < 8; j++)
            #pragma unroll
            for (int e = 0; e < 4; e++) acc[i][j][e] = 0.f;

    #pragma unroll
    for (int s = 0; s < 3; s++) {
        char* ad = aDst + s * STAGE_B;
        char* bd = bDst + s * STAGE_B;
        const bf16* as = aptr + s * 32;
        const bf16* bs = bptr + s * 32;
        #pragma unroll
        for (int c = 0; c < 4; c++) { cp16(ad + c * 16, as + c * 8); cp16(bd + c * 16, bs + c * 8); }
        asm volatile("cp.async.commit_group;");
    }

    #pragma unroll 1
    for (int it = 0; it < 16; it++) {
        if (it < 14)      asm volatile("cp.async.wait_group 2;");
        else if (it == 14) asm volatile("cp.async.wait_group 1;");
        else               asm volatile("cp.async.wait_group 0;");
        __syncthreads();
        if (it + 3 < 16) {
            int s = it + 3;
            char* ad = aDst + (s & 3) * STAGE_B;
            char* bd = bDst + (s & 3) * STAGE_B;
            const bf16* as = aptr + s * 32;
            const bf16* bs = bptr + s * 32;
            #pragma unroll
            for (int c = 0; c < 4; c++) { cp16(ad + c * 16, as + c * 8); cp16(bd + c * 16, bs + c * 8); }
            asm volatile("cp.async.commit_group;");
        }
        unsigned base = smBase + (unsigned)((it & 3) * STAGE_B);
        #pragma unroll
        for (int ks = 0; ks < 2; ks++) {
            unsigned a[4][4], b[8][2];
            #pragma unroll
            for (int mi = 0; mi < 4; mi++)
                ldsm4(a[mi][0], a[mi][1], a[mi][2], a[mi][3],
                      base + aOff + mi * (16 * 80) + ks * 32);
            #pragma unroll
            for (int pr = 0; pr < 4; pr++)
                ldsm4(b[2*pr][0], b[2*pr+1][0], b[2*pr][1], b[2*pr+1][1],
                      base + bOff + pr * (16 * 80) + ks * 32);
            #pragma unroll
            for (int mi = 0; mi < 4; mi++)
                #pragma unroll
                for (int ni = 0; ni < 8; ni++)
                    mma16816(acc[mi][ni], a[mi], b[ni]);
        }
    }

    #pragma unroll
    for (int mi = 0; mi < 4; mi++) {
        int r0 = brow + wm * 64 + mi * 16 + (lane >> 2);
        #pragma unroll
        for (int half = 0; half < 2; half++) {
            int r = r0 + half * 8;
            float sc = 1.f;
            if (MODE == 1) {
                int nseg = (r / Tt) % Nn;
                sc = fminf(fmaxf(rs[nseg], 0.f), 1.f);
            }
            #pragma unroll
            for (int ni = 0; ni < 8; ni++) {
                int c = bcol + wn * 64 + ni * 8 + (lane & 3) * 2;
                float x = acc[mi][ni][half * 2 + 0];
                float y = acc[mi][ni][half * 2 + 1];
                if (MODE == 0) {
                    *(__nv_bfloat162*)((bf16*)Cv + (size_t)r * 512 + c) =
                        __floats2bfloat162_rn(x, y);
                } else {
                    const float2 hv = *(const float2*)(hval + (size_t)r * 512 + c);
                    float2 o; o.x = hv.x + x * sc; o.y = hv.y + y * sc;
                    *(float2*)((float*)Cv + (size_t)r * 512 + c) = o;
                }
            }
        }
    }
}

// ---------------- mixed: smem-tiled sparse mix ----------------
__global__ void __launch_bounds__(256)
mixed2(const bf16* __restrict__ v, bf16* __restrict__ mixed) {
    __shared__ bf16 sv[128][128];
    __shared__ unsigned char su[128][16];
    __shared__ float swt[128][16];
    int nt = blockIdx.x, h = blockIdx.y, b = blockIdx.z;
    int tid = threadIdx.x, lane = tid & 31, w = tid >> 5;

    {
        int j = tid >> 1, tt = tid & 1;
        const uint4* src = (const uint4*)(v + ((size_t)(b * 128 + j) * 64 + nt * 2 + tt) * 512
                                            + h * 64);
        uint4* dst = (uint4*)&sv[j][tt * 64];
        #pragma unroll
        for (int c = 0; c < 8; c++) dst[c] = src[c];
    }
    {
        int base = (b * 8 + h) * 128;
        #pragma unroll
        for (int e = tid * 8; e < tid * 8 + 8; e++) {
            int i = e >> 4, kk = e & 15;
            int j = g_idx[(size_t)(base + i) * 16 + kk];
            su[i][kk] = (unsigned char)j;
            swt[i][kk] = g_attn[(size_t)(base + i) * 128 + j];
        }
    }
    __syncthreads();

    int tt = lane >> 4;
    for (int r = 0; r < 16; r++) {
        int i = w * 16 + r;
        float a0 = 0.f, a1 = 0.f, a2 = 0.f, a3 = 0.f;
        #pragma unroll
        for (int kk = 0; kk < 16; kk++) {
            int j = su[i][kk];
            float wt = swt[i][kk];
            uint2 vv = *(const uint2*)&sv[j][lane * 4];
            float2 f0 = __bfloat1622float2(*(__nv_bfloat162*)&vv.x);
            float2 f1 = __bfloat1622float2(*(__nv_bfloat162*)&vv.y);
            a0 = fmaf(wt, f0.x, a0); a1 = fmaf(wt, f0.y, a1);
            a2 = fmaf(wt, f1.x, a2); a3 = fmaf(wt, f1.y, a3);
        }
        int d = (lane & 15) * 4;
        __nv_bfloat162 o0 = __floats2bfloat162_rn(a0, a1);
        __nv_bfloat162 o1 = __floats2bfloat162_rn(a2, a3);
        uint2 ov; ov.x = *(unsigned*)&o0; ov.y = *(unsigned*)&o1;
        *(uint2*)(mixed + ((size_t)(b * 128 + i) * 64 + nt * 2 + tt) * 512 + h * 64 + d) = ov;
    }
}

// ---------------- head means ----------------
__global__ void means_kernel(float* __restrict__ out_attn, float* __restrict__ out_raw) {
    int idx = blockIdx.x * 256 + threadIdx.x;
    if (idx >= Bb * Nn * Nn) return;
    int b = idx / (Nn * Nn);
    int rem = idx % (Nn * Nn);
    float sa = 0.f, sr = 0.f;
    #pragma unroll
    for (int h = 0; h < Hh; h++) {
        size_t p = ((size_t)(b * Hh + h)) * Nn * Nn + rem;
        sa += g_attn[p];
        sr += g_raw[p];
    }
    out_attn[idx] = sa * (1.0f / Hh);
    out_raw[idx]  = sr * (1.0f / Hh);
}

// ---------------- launch: pure DAG (no hybrid), lazy-once streams ----------------
extern "C" void kernel_launch(void* const* d_in, const int* in_sizes, int n_in,
                              void* d_out, int out_size) {
    const float* h_val = (const float*)d_in[0];
    const float* h_map = (const float*)d_in[1];
    const float* adj   = (const float*)d_in[2];
    const float* q_w   = (const float*)d_in[3];
    const float* k_w   = (const float*)d_in[4];
    const float* v_w   = (const float*)d_in[5];
    const float* o_w   = (const float*)d_in[6];
    const float* rs    = (const float*)d_in[7];
    float* out = (float*)d_out;

    bf16 *hvb, *vwb, *owb, *v, *mixed;
    cudaGetSymbolAddress((void**)&hvb,   g_hvb);
    cudaGetSymbolAddress((void**)&vwb,   g_vwb);
    cudaGetSymbolAddress((void**)&owb,   g_owb);
    cudaGetSymbolAddress((void**)&v,     g_v);
    cudaGetSymbolAddress((void**)&mixed, g_mixed);

    // lazy one-time stream/event creation (happens on the correctness call,
    // before graph capture -> no allocation during capture, balance preserved)
    static cudaStream_t s1 = nullptr;
    static cudaEvent_t evF = nullptr, evW = nullptr, evScores = nullptr, evS1 = nullptr;
    if (s1 == nullptr) {
        cudaStreamCreateWithFlags(&s1, cudaStreamNonBlocking);
        cudaEventCreateWithFlags(&evF,      cudaEventDisableTiming);
        cudaEventCreateWithFlags(&evW,      cudaEventDisableTiming);
        cudaEventCreateWithFlags(&evScores, cudaEventDisableTiming);
        cudaEventCreateWithFlags(&evS1,     cudaEventDisableTiming);
        cudaFuncSetAttribute(mma_gemm4<0>, cudaFuncAttributeMaxDynamicSharedMemorySize, GSMEM);
        cudaFuncSetAttribute(mma_gemm4<1>, cudaFuncAttributeMaxDynamicSharedMemorySize, GSMEM);
    }

    cudaStream_t s0 = 0;

    // fork
    cudaEventRecord(evF, s0);
    cudaStreamWaitEvent(s1, evF, 0);

    // s1: weight converts + scalar scores chain + means (all cheap, off critical path)
    f2bf<<<(Dd*Dd/4 + 255)/256, 256, 0, s1>>>((const float4*)v_w, (uint2*)vwb, Dd*Dd/4);
    f2bf<<<(Dd*Dd/4 + 255)/256, 256, 0, s1>>>((const float4*)o_w, (uint2*)owb, Dd*Dd/4);
    cudaEventRecord(evW, s1);
    zmap_kernel<<<Bb * Nn, Dd, 0, s1>>>(h_map);
    qk_gemm<<<dim3(16, 16), 256, 0, s1>>>(q_w, k_w);
    scores2<<<dim3(2, Hh, Bb), 256, 0, s1>>>(adj);
    cudaEventRecord(evScores, s1);
    means_kernel<<<(MEAN_ELEMS + 255)/256, 256, 0, s1>>>(out + OUT0_ELEMS,
                                                         out + OUT0_ELEMS + MEAN_ELEMS);
    cudaEventRecord(evS1, s1);

    // s0: h_val convert + tensor v-GEMM (needs vwb by GEMM start)
    f2bf<<<(OUT0_ELEMS/4 + 255)/256, 256, 0, s0>>>((const float4*)h_val, (uint2*)hvb,
                                                   OUT0_ELEMS/4);
    cudaStreamWaitEvent(s0, evW, 0);
    mma_gemm4<0><<<dim3(4, 512), 128, GSMEM, s0>>>(hvb, vwb, (void*)v, nullptr, nullptr);

    // mixed needs scores
    cudaStreamWaitEvent(s0, evScores, 0);
    mixed2<<<dim3(32, Hh, Bb), 256, 0, s0>>>(v, mixed);

    // o-GEMM with fused residual
    mma_gemm4<1><<<dim3(4, 512), 128, GSMEM, s0>>>(mixed, owb, (void*)out, h_val, rs);

    // final join
    cudaStreamWaitEvent(s0, evS1, 0);
}